// round 1
// baseline (speedup 1.0000x reference)
#include <cuda_runtime.h>
#include <math.h>
#include <stdint.h>

// ---------------- constants ----------------
#define Bb 4
#define Nn 16384
#define Mm 1024
#define Cc 256
#define Kk 32
#define Pp (Bb*Mm*Kk)          // 131072
#define CIN1 264               // 259 padded to 264 (mult of 8)
#define COUT 512

// stats offsets in g_stats
#define SUM1 0
#define SQ1  128
#define SUM2 256
#define SQ2  260
#define SUML0 264              // layer l: SUML0 + l*1024 (sum), +512 (sq)
#define NSTATS (264 + 3*1024)

// ---------------- device scratch ----------------
__device__ __align__(128) float g_featT[(size_t)Bb*Nn*Cc];     // 67MB
__device__ __align__(128) float g_X0[(size_t)Pp*CIN1];         // 138MB
__device__ __align__(128) float g_Y1[(size_t)Pp*COUT];         // 268MB
__device__ __align__(128) float g_Y2[(size_t)Pp*COUT];         // 268MB
__device__ __align__(128) float g_h1[Bb*128*Mm];
__device__ __align__(128) float g_h2[Bb*3*Mm];
__device__ __align__(128) float g_q[Bb*Mm*3];
__device__ __align__(128) int   g_idx[Pp];
__device__ __align__(128) float g_W1r[COUT*CIN1];
__device__ __align__(128) float g_stats[NSTATS];
__device__ float g_sc1[128], g_bi1[128];
__device__ float g_sc2[4],   g_bi2[4];
__device__ float g_scL[3][COUT], g_biL[3][COUT];

// ---------------- helpers ----------------
__device__ __forceinline__ float wredsum(float v) {
    #pragma unroll
    for (int o = 16; o > 0; o >>= 1) v += __shfl_xor_sync(0xFFFFFFFFu, v, o);
    return v;
}

// ---------------- kernels ----------------
__global__ void k_zero() {
    for (int i = threadIdx.x; i < NSTATS; i += blockDim.x) g_stats[i] = 0.f;
}

__global__ void k_w1r(const float* __restrict__ w1) {
    int i = blockIdx.x * blockDim.x + threadIdx.x;
    if (i >= COUT * CIN1) return;
    int o = i / CIN1, c = i % CIN1;
    float v;
    if (c < 256)      v = w1[o * 259 + 3 + c];
    else if (c < 259) v = w1[o * 259 + (c - 256)];
    else              v = 0.f;
    g_W1r[i] = v;
}

// h1[b,o,m] = sum_c sw1[o,c]*feat[b,c,m]; accumulate per-channel stats.
// grid: B * (M/32) = 128 blocks, 256 threads (oy=tid>>5 in [0,8), mx=tid&31)
__global__ void k_s1(const float* __restrict__ feat, const float* __restrict__ sw1) {
    int blk = blockIdx.x;
    int b = blk >> 5;
    int m0 = (blk & 31) * 32;
    int tid = threadIdx.x;
    int mx = tid & 31, oy = tid >> 5;
    __shared__ float s_w[128][17];
    __shared__ float s_f[16][33];
    float acc[16];
    #pragma unroll
    for (int r = 0; r < 16; r++) acc[r] = 0.f;
    for (int c0 = 0; c0 < 256; c0 += 16) {
        __syncthreads();
        for (int idx = tid; idx < 128 * 16; idx += 256) {
            int o = idx >> 4, kk = idx & 15;
            s_w[o][kk] = sw1[o * 256 + c0 + kk];
        }
        for (int idx = tid; idx < 16 * 32; idx += 256) {
            int kk = idx >> 5, mm = idx & 31;
            s_f[kk][mm] = feat[((size_t)b * 256 + c0 + kk) * Mm + m0 + mm];
        }
        __syncthreads();
        #pragma unroll
        for (int r = 0; r < 16; r++) {
            int o = oy * 16 + r;
            #pragma unroll
            for (int kk = 0; kk < 16; kk++) acc[r] += s_w[o][kk] * s_f[kk][mx];
        }
    }
    #pragma unroll
    for (int r = 0; r < 16; r++) {
        int o = oy * 16 + r;
        float v = acc[r];
        g_h1[((size_t)b * 128 + o) * Mm + m0 + mx] = v;
        float s = wredsum(v), s2 = wredsum(v * v);
        if (mx == 0) {
            atomicAdd(&g_stats[SUM1 + o], s);
            atomicAdd(&g_stats[SQ1 + o], s2);
        }
    }
}

// finalize BN: scale = gamma*rsqrt(var+eps), bias = beta - mean*scale
__global__ void k_fin(int n, int sumOff, int sqOff,
                      const float* __restrict__ gamma, const float* __restrict__ beta,
                      int which, float count) {
    int i = blockIdx.x * blockDim.x + threadIdx.x;
    if (i >= n) return;
    float mean = g_stats[sumOff + i] / count;
    float var  = g_stats[sqOff + i] / count - mean * mean;
    var = fmaxf(var, 0.f);
    float s = gamma[i] * rsqrtf(var + 1e-5f);
    float bi = beta[i] - mean * s;
    float *sc, *bb;
    if      (which == 0) { sc = g_sc1;    bb = g_bi1; }
    else if (which == 1) { sc = g_sc2;    bb = g_bi2; }
    else if (which == 2) { sc = g_scL[0]; bb = g_biL[0]; }
    else if (which == 3) { sc = g_scL[1]; bb = g_biL[1]; }
    else                 { sc = g_scL[2]; bb = g_biL[2]; }
    sc[i] = s; bb[i] = bi;
}

// h2[b,j,m] = sum_o sw2[j,o]*relu(bn1(h1[b,o,m])); stats for 3 channels.
// grid: B*(M/128)=32 blocks, 128 threads
__global__ void k_s2(const float* __restrict__ sw2) {
    int b = blockIdx.x >> 3;
    int m0 = (blockIdx.x & 7) * 128;
    int tid = threadIdx.x;
    int m = m0 + tid;
    __shared__ float s_w[3][128];
    __shared__ float s_sc[128], s_bi[128];
    s_sc[tid] = g_sc1[tid];
    s_bi[tid] = g_bi1[tid];
    for (int i = tid; i < 384; i += 128) s_w[i / 128][i % 128] = sw2[i];
    __syncthreads();
    float a0 = 0.f, a1 = 0.f, a2 = 0.f;
    #pragma unroll 4
    for (int o = 0; o < 128; o++) {
        float h = g_h1[((size_t)b * 128 + o) * Mm + m];
        float x = fmaxf(h * s_sc[o] + s_bi[o], 0.f);
        a0 += s_w[0][o] * x;
        a1 += s_w[1][o] * x;
        a2 += s_w[2][o] * x;
    }
    g_h2[((size_t)b * 3 + 0) * Mm + m] = a0;
    g_h2[((size_t)b * 3 + 1) * Mm + m] = a1;
    g_h2[((size_t)b * 3 + 2) * Mm + m] = a2;
    float s, ss;
    s = wredsum(a0); ss = wredsum(a0 * a0);
    if ((tid & 31) == 0) { atomicAdd(&g_stats[SUM2 + 0], s); atomicAdd(&g_stats[SQ2 + 0], ss); }
    s = wredsum(a1); ss = wredsum(a1 * a1);
    if ((tid & 31) == 0) { atomicAdd(&g_stats[SUM2 + 1], s); atomicAdd(&g_stats[SQ2 + 1], ss); }
    s = wredsum(a2); ss = wredsum(a2 * a2);
    if ((tid & 31) == 0) { atomicAdd(&g_stats[SUM2 + 2], s); atomicAdd(&g_stats[SQ2 + 2], ss); }
}

// ball query: first K ascending indices with d2 < 1, pad with first (or 0).
// grid: B*M blocks, 256 threads
__global__ void k_neigh(const float* __restrict__ fxyz, const float* __restrict__ bxyz) {
    int bm = blockIdx.x;
    int b = bm >> 10;
    int m = bm & 1023;
    int tid = threadIdx.x;
    __shared__ float q[3];
    __shared__ int list[Kk];
    __shared__ int cnt;
    __shared__ unsigned masks[8];
    if (tid == 0) cnt = 0;
    if (tid < 3) {
        float h = g_h2[((size_t)b * 3 + tid) * Mm + m];
        float sft = fmaxf(h * g_sc2[tid] + g_bi2[tid], 0.f);
        float qq = fxyz[((size_t)b * Mm + m) * 3 + tid] + sft;
        q[tid] = qq;
        g_q[((size_t)b * Mm + m) * 3 + tid] = qq;
    }
    __syncthreads();
    float qx = q[0], qy = q[1], qz = q[2];
    const float* bx = bxyz + (size_t)b * Nn * 3;
    int lane = tid & 31, wid = tid >> 5;
    for (int ch = 0; ch < Nn / 256; ch++) {
        int j = ch * 256 + tid;
        float dx = bx[j * 3 + 0] - qx;
        float dy = bx[j * 3 + 1] - qy;
        float dz = bx[j * 3 + 2] - qz;
        bool p = (dx * dx + dy * dy + dz * dz) < 1.0f;
        unsigned mk = __ballot_sync(0xFFFFFFFFu, p);
        if (lane == 0) masks[wid] = mk;
        __syncthreads();
        int before = cnt;
        for (int w = 0; w < wid; w++) before += __popc(masks[w]);
        if (p) {
            int pos = before + __popc(mk & ((1u << lane) - 1u));
            if (pos < Kk) list[pos] = j;
        }
        int total = 0;
        #pragma unroll
        for (int w = 0; w < 8; w++) total += __popc(masks[w]);
        __syncthreads();
        if (tid == 0) cnt += total;
        __syncthreads();
        if (cnt >= Kk) break;
    }
    if (tid < Kk) {
        int c = cnt;
        int v;
        if (c == 0)        v = 0;
        else if (tid < c)  v = list[tid];
        else               v = list[0];
        g_idx[bm * Kk + tid] = v;
    }
}

// transpose backbone_features (B,C,N) -> featT (B,N,C)
// grid (N/32, C/32, B), block (32,8)
__global__ void k_transpose(const float* __restrict__ bf) {
    __shared__ float t[32][33];
    int b = blockIdx.z;
    int j0 = blockIdx.x * 32;
    int c0 = blockIdx.y * 32;
    int x = threadIdx.x, y = threadIdx.y;
    #pragma unroll
    for (int yy = y; yy < 32; yy += 8)
        t[yy][x] = bf[((size_t)b * Cc + c0 + yy) * Nn + j0 + x];
    __syncthreads();
    #pragma unroll
    for (int yy = y; yy < 32; yy += 8)
        g_featT[((size_t)b * Nn + j0 + yy) * Cc + c0 + x] = t[x][yy];
}

// build X0[p, 0..255]=featT[b,j,:], [256..258]=xyz_j - q, [259..263]=0
// grid B*M blocks, 256 threads (4 groups of 64)
__global__ void k_gather(const float* __restrict__ bxyz) {
    int bm = blockIdx.x;
    int b = bm >> 10;
    int tid = threadIdx.x;
    __shared__ int jl[Kk];
    __shared__ float q[3];
    if (tid < Kk) jl[tid] = g_idx[bm * Kk + tid];
    if (tid < 3) q[tid] = g_q[(size_t)bm * 3 + tid];
    __syncthreads();
    int grp = tid >> 6, t = tid & 63;
    for (int k = grp; k < Kk; k += 4) {
        int j = jl[k];
        size_t row = (size_t)(bm * Kk + k) * CIN1;
        const float4* src = (const float4*)(g_featT + ((size_t)b * Nn + j) * Cc);
        ((float4*)(g_X0 + row))[t] = src[t];
        if (t < 3)       g_X0[row + 256 + t] = bxyz[((size_t)b * Nn + j) * 3 + t] - q[t];
        else if (t < 8)  g_X0[row + 256 + t] = 0.f;
    }
}

// GEMM Y = act(A) @ W^T, 128x128 tile, BK=8, 256 threads, 8x8/thread.
// LAYER 0: A=X0 (raw), W=g_W1r, Y=g_Y1, CIN=264
// LAYER 1: A=g_Y1 (bn0+relu), W=w2,  Y=g_Y2, CIN=512
// LAYER 2: A=g_Y2 (bn1+relu), W=w3,  Y=g_Y1, CIN=512
template <int LAYER>
__global__ void __launch_bounds__(256, 2) k_gemm(const float* __restrict__ Wext) {
    constexpr int CIN = (LAYER == 0) ? CIN1 : COUT;
    const float* A = (LAYER == 0) ? g_X0 : (LAYER == 1 ? g_Y1 : g_Y2);
    float*       Y = (LAYER == 0) ? g_Y1 : (LAYER == 1 ? g_Y2 : g_Y1);
    const float* W = (LAYER == 0) ? g_W1r : Wext;
    const float* aSc = (LAYER == 1) ? g_scL[0] : g_scL[1];
    const float* aBi = (LAYER == 1) ? g_biL[0] : g_biL[1];
    const int sumOff = SUML0 + LAYER * 1024;
    const int sqOff  = sumOff + 512;

    __shared__ float As[8][128];
    __shared__ float Bs[8][128];
    __shared__ float sSc[COUT], sBi[COUT];
    __shared__ float sRed[8][128];
    __shared__ float sRed2[8][128];

    int tid = threadIdx.x;
    int tx = tid & 15, ty = tid >> 4;
    int row0 = blockIdx.x * 128;
    int col0 = blockIdx.y * 128;

    if (LAYER > 0) {
        for (int c = tid; c < CIN; c += 256) { sSc[c] = aSc[c]; sBi[c] = aBi[c]; }
        __syncthreads();
    }

    float acc[8][8];
    #pragma unroll
    for (int i = 0; i < 8; i++)
        #pragma unroll
        for (int j = 0; j < 8; j++) acc[i][j] = 0.f;

    int lr = tid >> 1;
    int lk = (tid & 1) * 4;
    const float* Ap = A + (size_t)(row0 + lr) * CIN + lk;
    const float* Wp = W + (size_t)(col0 + lr) * CIN + lk;

    for (int k0 = 0; k0 < CIN; k0 += 8) {
        float4 av = *(const float4*)(Ap + k0);
        float4 wv = *(const float4*)(Wp + k0);
        if (LAYER > 0) {
            int c = k0 + lk;
            av.x = fmaxf(av.x * sSc[c + 0] + sBi[c + 0], 0.f);
            av.y = fmaxf(av.y * sSc[c + 1] + sBi[c + 1], 0.f);
            av.z = fmaxf(av.z * sSc[c + 2] + sBi[c + 2], 0.f);
            av.w = fmaxf(av.w * sSc[c + 3] + sBi[c + 3], 0.f);
        }
        __syncthreads();
        As[lk + 0][lr] = av.x; As[lk + 1][lr] = av.y;
        As[lk + 2][lr] = av.z; As[lk + 3][lr] = av.w;
        Bs[lk + 0][lr] = wv.x; Bs[lk + 1][lr] = wv.y;
        Bs[lk + 2][lr] = wv.z; Bs[lk + 3][lr] = wv.w;
        __syncthreads();
        #pragma unroll
        for (int kk = 0; kk < 8; kk++) {
            float a[8], bb[8];
            *(float4*)(a)      = *(const float4*)&As[kk][ty * 8];
            *(float4*)(a + 4)  = *(const float4*)&As[kk][ty * 8 + 4];
            *(float4*)(bb)     = *(const float4*)&Bs[kk][tx * 8];
            *(float4*)(bb + 4) = *(const float4*)&Bs[kk][tx * 8 + 4];
            #pragma unroll
            for (int i = 0; i < 8; i++)
                #pragma unroll
                for (int j = 0; j < 8; j++) acc[i][j] += a[i] * bb[j];
        }
    }

    // write output tile
    #pragma unroll
    for (int i = 0; i < 8; i++) {
        size_t r = (size_t)(row0 + ty * 8 + i);
        float4 v0 = make_float4(acc[i][0], acc[i][1], acc[i][2], acc[i][3]);
        float4 v1 = make_float4(acc[i][4], acc[i][5], acc[i][6], acc[i][7]);
        *(float4*)&Y[r * COUT + col0 + tx * 8]     = v0;
        *(float4*)&Y[r * COUT + col0 + tx * 8 + 4] = v1;
    }

    // per-column partial stats
    float cs[8], cq[8];
    #pragma unroll
    for (int j = 0; j < 8; j++) {
        float s = 0.f, s2 = 0.f;
        #pragma unroll
        for (int i = 0; i < 8; i++) { float v = acc[i][j]; s += v; s2 += v * v; }
        cs[j] = s; cq[j] = s2;
    }
    int lane = tid & 31, wrp = tid >> 5;
    #pragma unroll
    for (int j = 0; j < 8; j++) {
        cs[j] += __shfl_xor_sync(0xFFFFFFFFu, cs[j], 16);
        cq[j] += __shfl_xor_sync(0xFFFFFFFFu, cq[j], 16);
    }
    if (lane < 16) {
        #pragma unroll
        for (int j = 0; j < 8; j++) {
            sRed[wrp][lane * 8 + j]  = cs[j];
            sRed2[wrp][lane * 8 + j] = cq[j];
        }
    }
    __syncthreads();
    if (tid < 128) {
        float s = 0.f, s2 = 0.f;
        #pragma unroll
        for (int w = 0; w < 8; w++) { s += sRed[w][tid]; s2 += sRed2[w][tid]; }
        atomicAdd(&g_stats[sumOff + col0 + tid], s);
        atomicAdd(&g_stats[sqOff + col0 + tid], s2);
    }
}

// out[bm, o] = relu(max_k (Y3 * sc + bi)); grid B*M, 256 threads
__global__ void k_final(float* __restrict__ out) {
    int bm = blockIdx.x;
    int tid = threadIdx.x;
    const float* base = g_Y1 + (size_t)bm * Kk * COUT;
    for (int o = tid; o < COUT; o += 256) {
        float s = g_scL[2][o], bi = g_biL[2][o];
        float mx = -1e30f;
        #pragma unroll 8
        for (int k = 0; k < Kk; k++) {
            float v = base[(size_t)k * COUT + o] * s + bi;
            mx = fmaxf(mx, v);
        }
        out[(size_t)bm * COUT + o] = fmaxf(mx, 0.f);
    }
}

// ---------------- launch ----------------
extern "C" void kernel_launch(void* const* d_in, const int* in_sizes, int n_in,
                              void* d_out, int out_size) {
    const float* ffps_xyz     = (const float*)d_in[0];
    const float* ffps_feature = (const float*)d_in[1];
    const float* backbone_xyz = (const float*)d_in[2];
    const float* backbone_feat= (const float*)d_in[3];
    const float* sw1 = (const float*)d_in[4];
    const float* sg1 = (const float*)d_in[5];
    const float* sb1 = (const float*)d_in[6];
    const float* sw2 = (const float*)d_in[7];
    const float* sg2 = (const float*)d_in[8];
    const float* sb2 = (const float*)d_in[9];
    const float* w1  = (const float*)d_in[10];
    const float* g1  = (const float*)d_in[11];
    const float* b1  = (const float*)d_in[12];
    const float* w2  = (const float*)d_in[13];
    const float* g2  = (const float*)d_in[14];
    const float* b2  = (const float*)d_in[15];
    const float* w3  = (const float*)d_in[16];
    const float* g3  = (const float*)d_in[17];
    const float* b3  = (const float*)d_in[18];
    float* out = (float*)d_out;

    k_zero<<<1, 256>>>();
    k_w1r<<<(COUT * CIN1 + 255) / 256, 256>>>(w1);

    // shift MLP
    k_s1<<<Bb * (Mm / 32), 256>>>(ffps_feature, sw1);
    k_fin<<<1, 128>>>(128, SUM1, SQ1, sg1, sb1, 0, (float)(Bb * Mm));
    k_s2<<<Bb * (Mm / 128), 128>>>(sw2);
    k_fin<<<1, 32>>>(3, SUM2, SQ2, sg2, sb2, 1, (float)(Bb * Mm));

    // ball query + gather
    k_neigh<<<Bb * Mm, 256>>>(ffps_xyz, backbone_xyz);
    k_transpose<<<dim3(Nn / 32, Cc / 32, Bb), dim3(32, 8)>>>(backbone_feat);
    k_gather<<<Bb * Mm, 256>>>(backbone_xyz);

    // conv layers
    dim3 ggrid(Pp / 128, COUT / 128);
    k_gemm<0><<<ggrid, 256>>>(nullptr);
    k_fin<<<2, 256>>>(512, SUML0 + 0 * 1024, SUML0 + 0 * 1024 + 512, g1, b1, 2, (float)Pp);
    k_gemm<1><<<ggrid, 256>>>(w2);
    k_fin<<<2, 256>>>(512, SUML0 + 1 * 1024, SUML0 + 1 * 1024 + 512, g2, b2, 3, (float)Pp);
    k_gemm<2><<<ggrid, 256>>>(w3);
    k_fin<<<2, 256>>>(512, SUML0 + 2 * 1024, SUML0 + 2 * 1024 + 512, g3, b3, 4, (float)Pp);

    // BN + relu + max over K
    k_final<<<Bb * Mm, 256>>>(out);
}

// round 2
// speedup vs baseline: 1.0027x; 1.0027x over previous
#include <cuda_runtime.h>
#include <math.h>
#include <stdint.h>

// ---------------- constants ----------------
#define Bb 4
#define Nn 16384
#define Mm 1024
#define Cc 256
#define Kk 32
#define Pp (Bb*Mm*Kk)          // 131072
#define CIN1 264               // 259 padded to 264 (mult of 8)
#define COUT 512

// stats offsets in g_stats
#define SUM1 0
#define SQ1  128
#define SUM2 256
#define SQ2  260
#define SUML0 264              // layer l: SUML0 + l*1024 (sum), +512 (sq)
#define NSTATS (264 + 3*1024)

// ---------------- device scratch ----------------
__device__ __align__(128) float g_featT[(size_t)Bb*Nn*Cc];     // 67MB
__device__ __align__(128) float g_X0[(size_t)Pp*CIN1];         // 138MB
__device__ __align__(128) float g_Y1[(size_t)Pp*COUT];         // 268MB
__device__ __align__(128) float g_Y2[(size_t)Pp*COUT];         // 268MB
__device__ __align__(128) float g_h1[Bb*128*Mm];
__device__ __align__(128) float g_h2[Bb*3*Mm];
__device__ __align__(128) float g_q[Bb*Mm*3];
__device__ __align__(128) int   g_idx[Pp];
__device__ __align__(128) float g_W1r[COUT*CIN1];
__device__ __align__(128) float g_stats[NSTATS];
__device__ float g_sc1[128], g_bi1[128];
__device__ float g_sc2[4],   g_bi2[4];
__device__ float g_scL[3][COUT], g_biL[3][COUT];

// ---------------- helpers ----------------
__device__ __forceinline__ float wredsum(float v) {
    #pragma unroll
    for (int o = 16; o > 0; o >>= 1) v += __shfl_xor_sync(0xFFFFFFFFu, v, o);
    return v;
}

// ---------------- kernels ----------------
__global__ void k_zero() {
    for (int i = threadIdx.x; i < NSTATS; i += blockDim.x) g_stats[i] = 0.f;
}

__global__ void k_w1r(const float* __restrict__ w1) {
    int i = blockIdx.x * blockDim.x + threadIdx.x;
    if (i >= COUT * CIN1) return;
    int o = i / CIN1, c = i % CIN1;
    float v;
    if (c < 256)      v = w1[o * 259 + 3 + c];
    else if (c < 259) v = w1[o * 259 + (c - 256)];
    else              v = 0.f;
    g_W1r[i] = v;
}

// h1[b,o,m] = sum_c sw1[o,c]*feat[b,c,m]; accumulate per-channel stats.
// grid: B * (M/32) = 128 blocks, 256 threads (oy=tid>>5 in [0,8), mx=tid&31)
__global__ void k_s1(const float* __restrict__ feat, const float* __restrict__ sw1) {
    int blk = blockIdx.x;
    int b = blk >> 5;
    int m0 = (blk & 31) * 32;
    int tid = threadIdx.x;
    int mx = tid & 31, oy = tid >> 5;
    __shared__ float s_w[128][17];
    __shared__ float s_f[16][33];
    float acc[16];
    #pragma unroll
    for (int r = 0; r < 16; r++) acc[r] = 0.f;
    for (int c0 = 0; c0 < 256; c0 += 16) {
        __syncthreads();
        for (int idx = tid; idx < 128 * 16; idx += 256) {
            int o = idx >> 4, kk = idx & 15;
            s_w[o][kk] = sw1[o * 256 + c0 + kk];
        }
        for (int idx = tid; idx < 16 * 32; idx += 256) {
            int kk = idx >> 5, mm = idx & 31;
            s_f[kk][mm] = feat[((size_t)b * 256 + c0 + kk) * Mm + m0 + mm];
        }
        __syncthreads();
        #pragma unroll
        for (int r = 0; r < 16; r++) {
            int o = oy * 16 + r;
            #pragma unroll
            for (int kk = 0; kk < 16; kk++) acc[r] += s_w[o][kk] * s_f[kk][mx];
        }
    }
    #pragma unroll
    for (int r = 0; r < 16; r++) {
        int o = oy * 16 + r;
        float v = acc[r];
        g_h1[((size_t)b * 128 + o) * Mm + m0 + mx] = v;
        float s = wredsum(v), s2 = wredsum(v * v);
        if (mx == 0) {
            atomicAdd(&g_stats[SUM1 + o], s);
            atomicAdd(&g_stats[SQ1 + o], s2);
        }
    }
}

// finalize BN: scale = gamma*rsqrt(var+eps), bias = beta - mean*scale
__global__ void k_fin(int n, int sumOff, int sqOff,
                      const float* __restrict__ gamma, const float* __restrict__ beta,
                      int which, float count) {
    int i = blockIdx.x * blockDim.x + threadIdx.x;
    if (i >= n) return;
    float mean = g_stats[sumOff + i] / count;
    float var  = g_stats[sqOff + i] / count - mean * mean;
    var = fmaxf(var, 0.f);
    float s = gamma[i] * rsqrtf(var + 1e-5f);
    float bi = beta[i] - mean * s;
    float *sc, *bb;
    if      (which == 0) { sc = g_sc1;    bb = g_bi1; }
    else if (which == 1) { sc = g_sc2;    bb = g_bi2; }
    else if (which == 2) { sc = g_scL[0]; bb = g_biL[0]; }
    else if (which == 3) { sc = g_scL[1]; bb = g_biL[1]; }
    else                 { sc = g_scL[2]; bb = g_biL[2]; }
    sc[i] = s; bb[i] = bi;
}

// h2[b,j,m] = sum_o sw2[j,o]*relu(bn1(h1[b,o,m])); stats for 3 channels.
// grid: B*(M/128)=32 blocks, 128 threads
__global__ void k_s2(const float* __restrict__ sw2) {
    int b = blockIdx.x >> 3;
    int m0 = (blockIdx.x & 7) * 128;
    int tid = threadIdx.x;
    int m = m0 + tid;
    __shared__ float s_w[3][128];
    __shared__ float s_sc[128], s_bi[128];
    s_sc[tid] = g_sc1[tid];
    s_bi[tid] = g_bi1[tid];
    for (int i = tid; i < 384; i += 128) s_w[i / 128][i % 128] = sw2[i];
    __syncthreads();
    float a0 = 0.f, a1 = 0.f, a2 = 0.f;
    #pragma unroll 4
    for (int o = 0; o < 128; o++) {
        float h = g_h1[((size_t)b * 128 + o) * Mm + m];
        float x = fmaxf(h * s_sc[o] + s_bi[o], 0.f);
        a0 += s_w[0][o] * x;
        a1 += s_w[1][o] * x;
        a2 += s_w[2][o] * x;
    }
    g_h2[((size_t)b * 3 + 0) * Mm + m] = a0;
    g_h2[((size_t)b * 3 + 1) * Mm + m] = a1;
    g_h2[((size_t)b * 3 + 2) * Mm + m] = a2;
    float s, ss;
    s = wredsum(a0); ss = wredsum(a0 * a0);
    if ((tid & 31) == 0) { atomicAdd(&g_stats[SUM2 + 0], s); atomicAdd(&g_stats[SQ2 + 0], ss); }
    s = wredsum(a1); ss = wredsum(a1 * a1);
    if ((tid & 31) == 0) { atomicAdd(&g_stats[SUM2 + 1], s); atomicAdd(&g_stats[SQ2 + 1], ss); }
    s = wredsum(a2); ss = wredsum(a2 * a2);
    if ((tid & 31) == 0) { atomicAdd(&g_stats[SUM2 + 2], s); atomicAdd(&g_stats[SQ2 + 2], ss); }
}

// ball query: first K ascending indices with d2 < 1, pad with first (or 0).
// grid: B*M blocks, 256 threads
__global__ void k_neigh(const float* __restrict__ fxyz, const float* __restrict__ bxyz) {
    int bm = blockIdx.x;
    int b = bm >> 10;
    int m = bm & 1023;
    int tid = threadIdx.x;
    __shared__ float q[3];
    __shared__ int list[Kk];
    __shared__ int cnt;
    __shared__ unsigned masks[8];
    if (tid == 0) cnt = 0;
    if (tid < 3) {
        float h = g_h2[((size_t)b * 3 + tid) * Mm + m];
        float sft = fmaxf(h * g_sc2[tid] + g_bi2[tid], 0.f);
        float qq = fxyz[((size_t)b * Mm + m) * 3 + tid] + sft;
        q[tid] = qq;
        g_q[((size_t)b * Mm + m) * 3 + tid] = qq;
    }
    __syncthreads();
    float qx = q[0], qy = q[1], qz = q[2];
    const float* bx = bxyz + (size_t)b * Nn * 3;
    int lane = tid & 31, wid = tid >> 5;
    for (int ch = 0; ch < Nn / 256; ch++) {
        int j = ch * 256 + tid;
        float dx = bx[j * 3 + 0] - qx;
        float dy = bx[j * 3 + 1] - qy;
        float dz = bx[j * 3 + 2] - qz;
        bool p = (dx * dx + dy * dy + dz * dz) < 1.0f;
        unsigned mk = __ballot_sync(0xFFFFFFFFu, p);
        if (lane == 0) masks[wid] = mk;
        __syncthreads();
        int before = cnt;
        for (int w = 0; w < wid; w++) before += __popc(masks[w]);
        if (p) {
            int pos = before + __popc(mk & ((1u << lane) - 1u));
            if (pos < Kk) list[pos] = j;
        }
        int total = 0;
        #pragma unroll
        for (int w = 0; w < 8; w++) total += __popc(masks[w]);
        __syncthreads();
        if (tid == 0) cnt += total;
        __syncthreads();
        if (cnt >= Kk) break;
    }
    if (tid < Kk) {
        int c = cnt;
        int v;
        if (c == 0)        v = 0;
        else if (tid < c)  v = list[tid];
        else               v = list[0];
        g_idx[bm * Kk + tid] = v;
    }
}

// transpose backbone_features (B,C,N) -> featT (B,N,C)
// grid (N/32, C/32, B), block (32,8)
__global__ void k_transpose(const float* __restrict__ bf) {
    __shared__ float t[32][33];
    int b = blockIdx.z;
    int j0 = blockIdx.x * 32;
    int c0 = blockIdx.y * 32;
    int x = threadIdx.x, y = threadIdx.y;
    #pragma unroll
    for (int yy = y; yy < 32; yy += 8)
        t[yy][x] = bf[((size_t)b * Cc + c0 + yy) * Nn + j0 + x];
    __syncthreads();
    #pragma unroll
    for (int yy = y; yy < 32; yy += 8)
        g_featT[((size_t)b * Nn + j0 + yy) * Cc + c0 + x] = t[x][yy];
}

// build X0[p, 0..255]=featT[b,j,:], [256..258]=xyz_j - q, [259..263]=0
// grid B*M blocks, 256 threads (4 groups of 64)
__global__ void k_gather(const float* __restrict__ bxyz) {
    int bm = blockIdx.x;
    int b = bm >> 10;
    int tid = threadIdx.x;
    __shared__ int jl[Kk];
    __shared__ float q[3];
    if (tid < Kk) jl[tid] = g_idx[bm * Kk + tid];
    if (tid < 3) q[tid] = g_q[(size_t)bm * 3 + tid];
    __syncthreads();
    int grp = tid >> 6, t = tid & 63;
    for (int k = grp; k < Kk; k += 4) {
        int j = jl[k];
        size_t row = (size_t)(bm * Kk + k) * CIN1;
        const float4* src = (const float4*)(g_featT + ((size_t)b * Nn + j) * Cc);
        ((float4*)(g_X0 + row))[t] = src[t];
        if (t < 3)       g_X0[row + 256 + t] = bxyz[((size_t)b * Nn + j) * 3 + t] - q[t];
        else if (t < 8)  g_X0[row + 256 + t] = 0.f;
    }
}

// GEMM Y = act(A) @ W^T, 128x128 tile, BK=8, 256 threads, 8x8/thread.
// LAYER 0: A=X0 (raw), W=g_W1r, Y=g_Y1, CIN=264
// LAYER 1: A=g_Y1 (bn0+relu), W=w2,  Y=g_Y2, CIN=512
// LAYER 2: A=g_Y2 (bn1+relu), W=w3,  Y=g_Y1, CIN=512
template <int LAYER>
__global__ void __launch_bounds__(256, 2) k_gemm(const float* __restrict__ Wext) {
    constexpr int CIN = (LAYER == 0) ? CIN1 : COUT;
    const float* A = (LAYER == 0) ? g_X0 : (LAYER == 1 ? g_Y1 : g_Y2);
    float*       Y = (LAYER == 0) ? g_Y1 : (LAYER == 1 ? g_Y2 : g_Y1);
    const float* W = (LAYER == 0) ? g_W1r : Wext;
    const float* aSc = (LAYER == 1) ? g_scL[0] : g_scL[1];
    const float* aBi = (LAYER == 1) ? g_biL[0] : g_biL[1];
    const int sumOff = SUML0 + LAYER * 1024;
    const int sqOff  = sumOff + 512;

    __shared__ float As[8][128];
    __shared__ float Bs[8][128];
    __shared__ float sSc[COUT], sBi[COUT];
    __shared__ float sRed[8][128];
    __shared__ float sRed2[8][128];

    int tid = threadIdx.x;
    int tx = tid & 15, ty = tid >> 4;
    int row0 = blockIdx.x * 128;
    int col0 = blockIdx.y * 128;

    if (LAYER > 0) {
        for (int c = tid; c < CIN; c += 256) { sSc[c] = aSc[c]; sBi[c] = aBi[c]; }
        __syncthreads();
    }

    float acc[8][8];
    #pragma unroll
    for (int i = 0; i < 8; i++)
        #pragma unroll
        for (int j = 0; j < 8; j++) acc[i][j] = 0.f;

    int lr = tid >> 1;
    int lk = (tid & 1) * 4;
    const float* Ap = A + (size_t)(row0 + lr) * CIN + lk;
    const float* Wp = W + (size_t)(col0 + lr) * CIN + lk;

    for (int k0 = 0; k0 < CIN; k0 += 8) {
        float4 av = *(const float4*)(Ap + k0);
        float4 wv = *(const float4*)(Wp + k0);
        if (LAYER > 0) {
            int c = k0 + lk;
            av.x = fmaxf(av.x * sSc[c + 0] + sBi[c + 0], 0.f);
            av.y = fmaxf(av.y * sSc[c + 1] + sBi[c + 1], 0.f);
            av.z = fmaxf(av.z * sSc[c + 2] + sBi[c + 2], 0.f);
            av.w = fmaxf(av.w * sSc[c + 3] + sBi[c + 3], 0.f);
        }
        __syncthreads();
        As[lk + 0][lr] = av.x; As[lk + 1][lr] = av.y;
        As[lk + 2][lr] = av.z; As[lk + 3][lr] = av.w;
        Bs[lk + 0][lr] = wv.x; Bs[lk + 1][lr] = wv.y;
        Bs[lk + 2][lr] = wv.z; Bs[lk + 3][lr] = wv.w;
        __syncthreads();
        #pragma unroll
        for (int kk = 0; kk < 8; kk++) {
            float a[8], bb[8];
            *(float4*)(a)      = *(const float4*)&As[kk][ty * 8];
            *(float4*)(a + 4)  = *(const float4*)&As[kk][ty * 8 + 4];
            *(float4*)(bb)     = *(const float4*)&Bs[kk][tx * 8];
            *(float4*)(bb + 4) = *(const float4*)&Bs[kk][tx * 8 + 4];
            #pragma unroll
            for (int i = 0; i < 8; i++)
                #pragma unroll
                for (int j = 0; j < 8; j++) acc[i][j] += a[i] * bb[j];
        }
    }

    // write output tile
    #pragma unroll
    for (int i = 0; i < 8; i++) {
        size_t r = (size_t)(row0 + ty * 8 + i);
        float4 v0 = make_float4(acc[i][0], acc[i][1], acc[i][2], acc[i][3]);
        float4 v1 = make_float4(acc[i][4], acc[i][5], acc[i][6], acc[i][7]);
        *(float4*)&Y[r * COUT + col0 + tx * 8]     = v0;
        *(float4*)&Y[r * COUT + col0 + tx * 8 + 4] = v1;
    }

    // per-column partial stats
    float cs[8], cq[8];
    #pragma unroll
    for (int j = 0; j < 8; j++) {
        float s = 0.f, s2 = 0.f;
        #pragma unroll
        for (int i = 0; i < 8; i++) { float v = acc[i][j]; s += v; s2 += v * v; }
        cs[j] = s; cq[j] = s2;
    }
    int lane = tid & 31, wrp = tid >> 5;
    #pragma unroll
    for (int j = 0; j < 8; j++) {
        cs[j] += __shfl_xor_sync(0xFFFFFFFFu, cs[j], 16);
        cq[j] += __shfl_xor_sync(0xFFFFFFFFu, cq[j], 16);
    }
    if (lane < 16) {
        #pragma unroll
        for (int j = 0; j < 8; j++) {
            sRed[wrp][lane * 8 + j]  = cs[j];
            sRed2[wrp][lane * 8 + j] = cq[j];
        }
    }
    __syncthreads();
    if (tid < 128) {
        float s = 0.f, s2 = 0.f;
        #pragma unroll
        for (int w = 0; w < 8; w++) { s += sRed[w][tid]; s2 += sRed2[w][tid]; }
        atomicAdd(&g_stats[sumOff + col0 + tid], s);
        atomicAdd(&g_stats[sqOff + col0 + tid], s2);
    }
}

// out[bm, o] = relu(max_k (Y3 * sc + bi)); grid B*M, 256 threads
__global__ void k_final(float* __restrict__ out) {
    int bm = blockIdx.x;
    int tid = threadIdx.x;
    const float* base = g_Y1 + (size_t)bm * Kk * COUT;
    for (int o = tid; o < COUT; o += 256) {
        float s = g_scL[2][o], bi = g_biL[2][o];
        float mx = -1e30f;
        #pragma unroll 8
        for (int k = 0; k < Kk; k++) {
            float v = base[(size_t)k * COUT + o] * s + bi;
            mx = fmaxf(mx, v);
        }
        out[(size_t)bm * COUT + o] = fmaxf(mx, 0.f);
    }
}

// ---------------- launch ----------------
extern "C" void kernel_launch(void* const* d_in, const int* in_sizes, int n_in,
                              void* d_out, int out_size) {
    const float* ffps_xyz     = (const float*)d_in[0];
    const float* ffps_feature = (const float*)d_in[1];
    const float* backbone_xyz = (const float*)d_in[2];
    const float* backbone_feat= (const float*)d_in[3];
    const float* sw1 = (const float*)d_in[4];
    const float* sg1 = (const float*)d_in[5];
    const float* sb1 = (const float*)d_in[6];
    const float* sw2 = (const float*)d_in[7];
    const float* sg2 = (const float*)d_in[8];
    const float* sb2 = (const float*)d_in[9];
    const float* w1  = (const float*)d_in[10];
    const float* g1  = (const float*)d_in[11];
    const float* b1  = (const float*)d_in[12];
    const float* w2  = (const float*)d_in[13];
    const float* g2  = (const float*)d_in[14];
    const float* b2  = (const float*)d_in[15];
    const float* w3  = (const float*)d_in[16];
    const float* g3  = (const float*)d_in[17];
    const float* b3  = (const float*)d_in[18];
    float* out = (float*)d_out;

    k_zero<<<1, 256>>>();
    k_w1r<<<(COUT * CIN1 + 255) / 256, 256>>>(w1);

    // shift MLP
    k_s1<<<Bb * (Mm / 32), 256>>>(ffps_feature, sw1);
    k_fin<<<1, 128>>>(128, SUM1, SQ1, sg1, sb1, 0, (float)(Bb * Mm));
    k_s2<<<Bb * (Mm / 128), 128>>>(sw2);
    k_fin<<<1, 32>>>(3, SUM2, SQ2, sg2, sb2, 1, (float)(Bb * Mm));

    // ball query + gather
    k_neigh<<<Bb * Mm, 256>>>(ffps_xyz, backbone_xyz);
    k_transpose<<<dim3(Nn / 32, Cc / 32, Bb), dim3(32, 8)>>>(backbone_feat);
    k_gather<<<Bb * Mm, 256>>>(backbone_xyz);

    // conv layers
    dim3 ggrid(Pp / 128, COUT / 128);
    k_gemm<0><<<ggrid, 256>>>(nullptr);
    k_fin<<<2, 256>>>(512, SUML0 + 0 * 1024, SUML0 + 0 * 1024 + 512, g1, b1, 2, (float)Pp);
    k_gemm<1><<<ggrid, 256>>>(w2);
    k_fin<<<2, 256>>>(512, SUML0 + 1 * 1024, SUML0 + 1 * 1024 + 512, g2, b2, 3, (float)Pp);
    k_gemm<2><<<ggrid, 256>>>(w3);
    k_fin<<<2, 256>>>(512, SUML0 + 2 * 1024, SUML0 + 2 * 1024 + 512, g3, b3, 4, (float)Pp);

    // BN + relu + max over K
    k_final<<<Bb * Mm, 256>>>(out);
}

// round 4
// speedup vs baseline: 2.2067x; 2.2008x over previous
#include <cuda_runtime.h>
#include <math.h>
#include <stdint.h>

#define Bb 4
#define Nn 16384
#define Mm 1024
#define Cc 256
#define Kk 32
#define Pp (Bb*Mm*Kk)
#define CIN0 288
#define COUT 512

#define SUM1 0
#define SQ1  128
#define SUM2 256
#define SQ2  260
#define SUML0 264
#define NSTATS (264 + 3*1024)

__device__ __align__(128) float g_featT[(size_t)Bb*Nn*Cc];
__device__ __align__(128) float g_X0[(size_t)Pp*CIN0];
__device__ __align__(128) float g_Y1[(size_t)Pp*COUT];
__device__ __align__(128) float g_Y2[(size_t)Pp*COUT];
__device__ __align__(128) float g_h1[Bb*128*Mm];
__device__ __align__(128) float g_h2[Bb*3*Mm];
__device__ __align__(128) float g_q[Bb*Mm*3];
__device__ __align__(128) int   g_idx[Pp];
__device__ __align__(128) float g_W1r[COUT*CIN0];
__device__ __align__(128) float g_stats[NSTATS];
__device__ float g_sc1[128], g_bi1[128];
__device__ float g_sc2[4],   g_bi2[4];
__device__ float g_scL[3][COUT], g_biL[3][COUT];

__device__ __forceinline__ float wredsum(float v) {
    #pragma unroll
    for (int o = 16; o > 0; o >>= 1) v += __shfl_xor_sync(0xFFFFFFFFu, v, o);
    return v;
}
__device__ __forceinline__ uint32_t f2tf32(float x) {
    uint32_t y;
    asm("cvt.rna.tf32.f32 %0, %1;" : "=r"(y) : "f"(x));
    return y;
}
__device__ __forceinline__ void mma_tf32(float* d, const uint32_t* a, const uint32_t* b) {
    asm volatile("mma.sync.aligned.m16n8k8.row.col.f32.tf32.tf32.f32 "
                 "{%0,%1,%2,%3}, {%4,%5,%6,%7}, {%8,%9}, {%0,%1,%2,%3};"
                 : "+f"(d[0]), "+f"(d[1]), "+f"(d[2]), "+f"(d[3])
                 : "r"(a[0]), "r"(a[1]), "r"(a[2]), "r"(a[3]), "r"(b[0]), "r"(b[1]));
}

__global__ void k_zero() {
    for (int i = threadIdx.x; i < NSTATS; i += blockDim.x) g_stats[i] = 0.f;
}

__global__ void k_w1r(const float* __restrict__ w1) {
    int i = blockIdx.x * blockDim.x + threadIdx.x;
    if (i >= COUT * CIN0) return;
    int o = i / CIN0, c = i % CIN0;
    float v;
    if (c < 256)      v = w1[o * 259 + 3 + c];
    else if (c < 259) v = w1[o * 259 + (c - 256)];
    else              v = 0.f;
    g_W1r[i] = v;
}

__global__ void k_s1(const float* __restrict__ feat, const float* __restrict__ sw1) {
    int blk = blockIdx.x;
    int b = blk >> 5;
    int m0 = (blk & 31) * 32;
    int tid = threadIdx.x;
    int mx = tid & 31, oy = tid >> 5;
    __shared__ float s_w[128][17];
    __shared__ float s_f[16][33];
    float acc[16];
    #pragma unroll
    for (int r = 0; r < 16; r++) acc[r] = 0.f;
    for (int c0 = 0; c0 < 256; c0 += 16) {
        __syncthreads();
        for (int idx = tid; idx < 128 * 16; idx += 256) {
            int o = idx >> 4, kk = idx & 15;
            s_w[o][kk] = sw1[o * 256 + c0 + kk];
        }
        for (int idx = tid; idx < 16 * 32; idx += 256) {
            int kk = idx >> 5, mm = idx & 31;
            s_f[kk][mm] = feat[((size_t)b * 256 + c0 + kk) * Mm + m0 + mm];
        }
        __syncthreads();
        #pragma unroll
        for (int r = 0; r < 16; r++) {
            int o = oy * 16 + r;
            #pragma unroll
            for (int kk = 0; kk < 16; kk++) acc[r] += s_w[o][kk] * s_f[kk][mx];
        }
    }
    #pragma unroll
    for (int r = 0; r < 16; r++) {
        int o = oy * 16 + r;
        float v = acc[r];
        g_h1[((size_t)b * 128 + o) * Mm + m0 + mx] = v;
        float s = wredsum(v), s2 = wredsum(v * v);
        if (mx == 0) {
            atomicAdd(&g_stats[SUM1 + o], s);
            atomicAdd(&g_stats[SQ1 + o], s2);
        }
    }
}

__global__ void k_fin(int n, int sumOff, int sqOff,
                      const float* __restrict__ gamma, const float* __restrict__ beta,
                      int which, float count) {
    int i = blockIdx.x * blockDim.x + threadIdx.x;
    if (i >= n) return;
    float mean = g_stats[sumOff + i] / count;
    float var  = g_stats[sqOff + i] / count - mean * mean;
    var = fmaxf(var, 0.f);
    float s = gamma[i] * rsqrtf(var + 1e-5f);
    float bi = beta[i] - mean * s;
    float *sc, *bb;
    if      (which == 0) { sc = g_sc1;    bb = g_bi1; }
    else if (which == 1) { sc = g_sc2;    bb = g_bi2; }
    else if (which == 2) { sc = g_scL[0]; bb = g_biL[0]; }
    else if (which == 3) { sc = g_scL[1]; bb = g_biL[1]; }
    else                 { sc = g_scL[2]; bb = g_biL[2]; }
    sc[i] = s; bb[i] = bi;
}

__global__ void k_s2(const float* __restrict__ sw2) {
    int b = blockIdx.x >> 3;
    int m0 = (blockIdx.x & 7) * 128;
    int tid = threadIdx.x;
    int m = m0 + tid;
    __shared__ float s_w[3][128];
    __shared__ float s_sc[128], s_bi[128];
    s_sc[tid] = g_sc1[tid];
    s_bi[tid] = g_bi1[tid];
    for (int i = tid; i < 384; i += 128) s_w[i / 128][i % 128] = sw2[i];
    __syncthreads();
    float a0 = 0.f, a1 = 0.f, a2 = 0.f;
    #pragma unroll 4
    for (int o = 0; o < 128; o++) {
        float h = g_h1[((size_t)b * 128 + o) * Mm + m];
        float x = fmaxf(h * s_sc[o] + s_bi[o], 0.f);
        a0 += s_w[0][o] * x;
        a1 += s_w[1][o] * x;
        a2 += s_w[2][o] * x;
    }
    g_h2[((size_t)b * 3 + 0) * Mm + m] = a0;
    g_h2[((size_t)b * 3 + 1) * Mm + m] = a1;
    g_h2[((size_t)b * 3 + 2) * Mm + m] = a2;
    float s, ss;
    s = wredsum(a0); ss = wredsum(a0 * a0);
    if ((tid & 31) == 0) { atomicAdd(&g_stats[SUM2 + 0], s); atomicAdd(&g_stats[SQ2 + 0], ss); }
    s = wredsum(a1); ss = wredsum(a1 * a1);
    if ((tid & 31) == 0) { atomicAdd(&g_stats[SUM2 + 1], s); atomicAdd(&g_stats[SQ2 + 1], ss); }
    s = wredsum(a2); ss = wredsum(a2 * a2);
    if ((tid & 31) == 0) { atomicAdd(&g_stats[SUM2 + 2], s); atomicAdd(&g_stats[SQ2 + 2], ss); }
}

__global__ void k_neigh(const float* __restrict__ fxyz, const float* __restrict__ bxyz) {
    int bm = blockIdx.x;
    int b = bm >> 10;
    int m = bm & 1023;
    int tid = threadIdx.x;
    __shared__ float q[3];
    __shared__ int list[Kk];
    __shared__ int cnt;
    __shared__ unsigned masks[8];
    if (tid == 0) cnt = 0;
    if (tid < 3) {
        float h = g_h2[((size_t)b * 3 + tid) * Mm + m];
        float sft = fmaxf(h * g_sc2[tid] + g_bi2[tid], 0.f);
        float qq = fxyz[((size_t)b * Mm + m) * 3 + tid] + sft;
        q[tid] = qq;
        g_q[((size_t)b * Mm + m) * 3 + tid] = qq;
    }
    __syncthreads();
    float qx = q[0], qy = q[1], qz = q[2];
    const float* bx = bxyz + (size_t)b * Nn * 3;
    int lane = tid & 31, wid = tid >> 5;
    for (int ch = 0; ch < Nn / 256; ch++) {
        int j = ch * 256 + tid;
        float dx = bx[j * 3 + 0] - qx;
        float dy = bx[j * 3 + 1] - qy;
        float dz = bx[j * 3 + 2] - qz;
        bool p = (dx * dx + dy * dy + dz * dz) < 1.0f;
        unsigned mk = __ballot_sync(0xFFFFFFFFu, p);
        if (lane == 0) masks[wid] = mk;
        __syncthreads();
        int before = cnt;
        for (int w = 0; w < wid; w++) before += __popc(masks[w]);
        if (p) {
            int pos = before + __popc(mk & ((1u << lane) - 1u));
            if (pos < Kk) list[pos] = j;
        }
        int total = 0;
        #pragma unroll
        for (int w = 0; w < 8; w++) total += __popc(masks[w]);
        __syncthreads();
        if (tid == 0) cnt += total;
        __syncthreads();
        if (cnt >= Kk) break;
    }
    if (tid < Kk) {
        int c = cnt;
        int v;
        if (c == 0)        v = 0;
        else if (tid < c)  v = list[tid];
        else               v = list[0];
        g_idx[bm * Kk + tid] = v;
    }
}

__global__ void k_transpose(const float* __restrict__ bf) {
    __shared__ float t[32][33];
    int b = blockIdx.z;
    int j0 = blockIdx.x * 32;
    int c0 = blockIdx.y * 32;
    int x = threadIdx.x, y = threadIdx.y;
    #pragma unroll
    for (int yy = y; yy < 32; yy += 8)
        t[yy][x] = bf[((size_t)b * Cc + c0 + yy) * Nn + j0 + x];
    __syncthreads();
    #pragma unroll
    for (int yy = y; yy < 32; yy += 8)
        g_featT[((size_t)b * Nn + j0 + yy) * Cc + c0 + x] = t[x][yy];
}

__global__ void k_gather(const float* __restrict__ bxyz) {
    int bm = blockIdx.x;
    int b = bm >> 10;
    int tid = threadIdx.x;
    __shared__ int jl[Kk];
    __shared__ float q[3];
    if (tid < Kk) jl[tid] = g_idx[bm * Kk + tid];
    if (tid < 3) q[tid] = g_q[(size_t)bm * 3 + tid];
    __syncthreads();
    int grp = tid >> 6, t = tid & 63;
    for (int k = grp; k < Kk; k += 4) {
        int j = jl[k];
        size_t row = (size_t)(bm * Kk + k) * CIN0;
        const float4* src = (const float4*)(g_featT + ((size_t)b * Nn + j) * Cc);
        ((float4*)(g_X0 + row))[t] = src[t];
        if (t < 3)       g_X0[row + 256 + t] = bxyz[((size_t)b * Nn + j) * 3 + t] - q[t];
        else if (t < 32) g_X0[row + 256 + t] = 0.f;
    }
}

// ---- tf32 mma.sync GEMM: Y[P,512] = act(A[P,CIN]) @ W[512,CIN]^T ----
// CTA 128x128, 8 warps (wm=wrp&3 -> 32 rows, wn=wrp>>2 -> 64 cols), KC=16.
#define KC 16
#define LDP 20   // padded row stride in floats (bank-conflict-free fragments)

template <int LAYER>
__global__ void __launch_bounds__(256, 2) k_mma(const float* __restrict__ Wext) {
    constexpr int CIN = (LAYER == 0) ? CIN0 : COUT;
    constexpr int NCH = CIN / KC;
    constexpr int sumOff = SUML0 + LAYER * 1024;
    constexpr int sqOff  = sumOff + 512;
    const float* A = (LAYER == 0) ? g_X0 : (LAYER == 1 ? g_Y1 : g_Y2);
    float*       Y = (LAYER == 0) ? g_Y1 : (LAYER == 1 ? g_Y2 : g_Y1);
    const float* W = (LAYER == 0) ? g_W1r : Wext;

    __shared__ float sA[2][128 * LDP];
    __shared__ float sB[2][128 * LDP];
    __shared__ float sSc[COUT], sBi[COUT];
    __shared__ float sPs[128], sPq[128];

    int tid = threadIdx.x;
    int lane = tid & 31, wrp = tid >> 5;
    int g = lane >> 2, t = lane & 3;
    int wm = wrp & 3, wn = wrp >> 2;
    int row0 = blockIdx.y * 128;
    int col0 = blockIdx.x * 128;

    if (LAYER > 0) {
        for (int c = tid; c < COUT; c += 256) {
            sSc[c] = g_scL[LAYER - 1][c];
            sBi[c] = g_biL[LAYER - 1][c];
        }
    }
    if (tid < 128) { sPs[tid] = 0.f; sPq[tid] = 0.f; }
    __syncthreads();

    float acc[2][8][4];
    #pragma unroll
    for (int i = 0; i < 2; i++)
        #pragma unroll
        for (int j = 0; j < 8; j++)
            #pragma unroll
            for (int r = 0; r < 4; r++) acc[i][j][r] = 0.f;

    // staging indices (2 float4 each for A and B)
    int fr = tid >> 2;           // row within tile for float4 idx = tid
    int fq = tid & 3;            // quad within row
    float4 aS[2], bS[2];

    auto ldg = [&](int c) {
        #pragma unroll
        for (int i = 0; i < 2; i++) {
            int r = fr + i * 64;
            aS[i] = *(const float4*)(A + (size_t)(row0 + r) * CIN + c * KC + fq * 4);
            bS[i] = *(const float4*)(W + (size_t)(col0 + r) * CIN + c * KC + fq * 4);
        }
        if (LAYER > 0) {
            int cc = c * KC + fq * 4;
            float4 sc = *(const float4*)&sSc[cc];
            float4 bi = *(const float4*)&sBi[cc];
            #pragma unroll
            for (int i = 0; i < 2; i++) {
                aS[i].x = fmaxf(aS[i].x * sc.x + bi.x, 0.f);
                aS[i].y = fmaxf(aS[i].y * sc.y + bi.y, 0.f);
                aS[i].z = fmaxf(aS[i].z * sc.z + bi.z, 0.f);
                aS[i].w = fmaxf(aS[i].w * sc.w + bi.w, 0.f);
            }
        }
    };
    auto sts = [&](int s) {
        #pragma unroll
        for (int i = 0; i < 2; i++) {
            int r = fr + i * 64;
            uint4 va = make_uint4(f2tf32(aS[i].x), f2tf32(aS[i].y), f2tf32(aS[i].z), f2tf32(aS[i].w));
            uint4 vb = make_uint4(f2tf32(bS[i].x), f2tf32(bS[i].y), f2tf32(bS[i].z), f2tf32(bS[i].w));
            *(uint4*)&sA[s][r * LDP + fq * 4] = va;
            *(uint4*)&sB[s][r * LDP + fq * 4] = vb;
        }
    };
    auto compute = [&](int s) {
        const float* As = sA[s];
        const float* Bs = sB[s];
        #pragma unroll
        for (int ks = 0; ks < 2; ks++) {
            uint32_t af[2][4], bf[8][2];
            #pragma unroll
            for (int i = 0; i < 2; i++) {
                int rb = wm * 32 + i * 16 + g;
                af[i][0] = __float_as_uint(As[(rb    ) * LDP + ks * 8 + t]);
                af[i][1] = __float_as_uint(As[(rb + 8) * LDP + ks * 8 + t]);
                af[i][2] = __float_as_uint(As[(rb    ) * LDP + ks * 8 + t + 4]);
                af[i][3] = __float_as_uint(As[(rb + 8) * LDP + ks * 8 + t + 4]);
            }
            #pragma unroll
            for (int j = 0; j < 8; j++) {
                int rb = wn * 64 + j * 8 + g;
                bf[j][0] = __float_as_uint(Bs[rb * LDP + ks * 8 + t]);
                bf[j][1] = __float_as_uint(Bs[rb * LDP + ks * 8 + t + 4]);
            }
            #pragma unroll
            for (int i = 0; i < 2; i++)
                #pragma unroll
                for (int j = 0; j < 8; j++)
                    mma_tf32(acc[i][j], af[i], bf[j]);
        }
    };

    ldg(0);
    sts(0);
    __syncthreads();
    for (int c = 0; c < NCH; c++) {
        int s = c & 1;
        if (c + 1 < NCH) ldg(c + 1);
        compute(s);
        if (c + 1 < NCH) {
            __syncthreads();
            sts((c + 1) & 1);
            __syncthreads();
        }
    }

    // ---- epilogue: store Y + column stats ----
    #pragma unroll
    for (int i = 0; i < 2; i++) {
        int rlo = row0 + wm * 32 + i * 16 + g;
        #pragma unroll
        for (int j = 0; j < 8; j++) {
            int col = col0 + wn * 64 + j * 8 + t * 2;
            float2 lo = make_float2(acc[i][j][0], acc[i][j][1]);
            float2 hi = make_float2(acc[i][j][2], acc[i][j][3]);
            *(float2*)&Y[(size_t)rlo * COUT + col]       = lo;
            *(float2*)&Y[(size_t)(rlo + 8) * COUT + col] = hi;
        }
    }
    #pragma unroll
    for (int j = 0; j < 8; j++) {
        #pragma unroll
        for (int rb = 0; rb < 2; rb++) {
            float s = 0.f, q2 = 0.f;
            #pragma unroll
            for (int i = 0; i < 2; i++) {
                float v0 = acc[i][j][rb], v1 = acc[i][j][rb + 2];
                s += v0 + v1;
                q2 += v0 * v0 + v1 * v1;
            }
            s  += __shfl_xor_sync(0xFFFFFFFFu, s, 4);
            q2 += __shfl_xor_sync(0xFFFFFFFFu, q2, 4);
            s  += __shfl_xor_sync(0xFFFFFFFFu, s, 8);
            q2 += __shfl_xor_sync(0xFFFFFFFFu, q2, 8);
            s  += __shfl_xor_sync(0xFFFFFFFFu, s, 16);
            q2 += __shfl_xor_sync(0xFFFFFFFFu, q2, 16);
            if (g == 0) {
                int cc = wn * 64 + j * 8 + t * 2 + rb;
                atomicAdd(&sPs[cc], s);
                atomicAdd(&sPq[cc], q2);
            }
        }
    }
    __syncthreads();
    if (tid < 128) {
        atomicAdd(&g_stats[sumOff + col0 + tid], sPs[tid]);
        atomicAdd(&g_stats[sqOff  + col0 + tid], sPq[tid]);
    }
}

__global__ void k_final(float* __restrict__ out) {
    int bm = blockIdx.x;
    int tid = threadIdx.x;
    const float* base = g_Y1 + (size_t)bm * Kk * COUT;
    for (int o = tid; o < COUT; o += 256) {
        float s = g_scL[2][o], bi = g_biL[2][o];
        float mx = -1e30f;
        #pragma unroll 8
        for (int k = 0; k < Kk; k++) {
            float v = base[(size_t)k * COUT + o] * s + bi;
            mx = fmaxf(mx, v);
        }
        out[(size_t)bm * COUT + o] = fmaxf(mx, 0.f);
    }
}

extern "C" void kernel_launch(void* const* d_in, const int* in_sizes, int n_in,
                              void* d_out, int out_size) {
    const float* ffps_xyz     = (const float*)d_in[0];
    const float* ffps_feature = (const float*)d_in[1];
    const float* backbone_xyz = (const float*)d_in[2];
    const float* backbone_feat= (const float*)d_in[3];
    const float* sw1 = (const float*)d_in[4];
    const float* sg1 = (const float*)d_in[5];
    const float* sb1 = (const float*)d_in[6];
    const float* sw2 = (const float*)d_in[7];
    const float* sg2 = (const float*)d_in[8];
    const float* sb2 = (const float*)d_in[9];
    const float* w1  = (const float*)d_in[10];
    const float* g1  = (const float*)d_in[11];
    const float* b1  = (const float*)d_in[12];
    const float* w2  = (const float*)d_in[13];
    const float* g2  = (const float*)d_in[14];
    const float* b2  = (const float*)d_in[15];
    const float* w3  = (const float*)d_in[16];
    const float* g3  = (const float*)d_in[17];
    const float* b3  = (const float*)d_in[18];
    float* out = (float*)d_out;

    k_zero<<<1, 256>>>();
    k_w1r<<<(COUT * CIN0 + 255) / 256, 256>>>(w1);
    k_s1<<<Bb * (Mm / 32), 256>>>(ffps_feature, sw1);
    k_fin<<<1, 128>>>(128, SUM1, SQ1, sg1, sb1, 0, (float)(Bb * Mm));
    k_s2<<<Bb * (Mm / 128), 128>>>(sw2);
    k_fin<<<1, 32>>>(3, SUM2, SQ2, sg2, sb2, 1, (float)(Bb * Mm));
    k_neigh<<<Bb * Mm, 256>>>(ffps_xyz, backbone_xyz);
    k_transpose<<<dim3(Nn / 32, Cc / 32, Bb), dim3(32, 8)>>>(backbone_feat);
    k_gather<<<Bb * Mm, 256>>>(backbone_xyz);

    dim3 grid(COUT / 128, Pp / 128);   // x = N block (fast) for A-tile L2 reuse
    k_mma<0><<<grid, 256>>>(nullptr);
    k_fin<<<2, 256>>>(512, SUML0 + 0 * 1024, SUML0 + 0 * 1024 + 512, g1, b1, 2, (float)Pp);
    k_mma<1><<<grid, 256>>>(w2);
    k_fin<<<2, 256>>>(512, SUML0 + 1 * 1024, SUML0 + 1 * 1024 + 512, g2, b2, 3, (float)Pp);
    k_mma<2><<<grid, 256>>>(w3);
    k_fin<<<2, 256>>>(512, SUML0 + 2 * 1024, SUML0 + 2 * 1024 + 512, g3, b3, 4, (float)Pp);

    k_final<<<Bb * Mm, 256>>>(out);
}

// round 5
// speedup vs baseline: 3.5065x; 1.5891x over previous
#include <cuda_runtime.h>
#include <cuda_fp16.h>
#include <math.h>
#include <stdint.h>

#define Bb 4
#define Nn 16384
#define Mm 1024
#define Cc 256
#define Kk 32
#define Pp (Bb*Mm*Kk)
#define CIN0 288
#define COUT 512

#define SUM1 0
#define SQ1  128
#define SUM2 256
#define SQ2  260
#define SUML0 264
#define NSTATS (264 + 3*1024)

__device__ __align__(128) float  g_featT[(size_t)Bb*Nn*Cc];
__device__ __align__(128) __half g_Y1[(size_t)Pp*COUT];
__device__ __align__(128) __half g_Y2[(size_t)Pp*COUT];
__device__ __align__(128) float  g_h1[Bb*128*Mm];
__device__ __align__(128) float  g_h2[Bb*3*Mm];
__device__ __align__(128) float  g_q[Bb*Mm*3];
__device__ __align__(128) int    g_idx[Pp];
__device__ __align__(128) float  g_W1r[COUT*CIN0];
__device__ __align__(128) float  g_stats[NSTATS];
__device__ float g_sc1[128], g_bi1[128];
__device__ float g_sc2[4],   g_bi2[4];
__device__ float g_scL[3][COUT], g_biL[3][COUT];

__device__ __forceinline__ float wredsum(float v) {
    #pragma unroll
    for (int o = 16; o > 0; o >>= 1) v += __shfl_xor_sync(0xFFFFFFFFu, v, o);
    return v;
}
__device__ __forceinline__ uint32_t packh2(float a, float b) {
    __half2 h = __floats2half2_rn(a, b);
    return *(uint32_t*)&h;
}
__device__ __forceinline__ void mma_f16(float* d, const uint32_t* a, const uint32_t* b) {
    asm volatile("mma.sync.aligned.m16n8k16.row.col.f32.f16.f16.f32 "
                 "{%0,%1,%2,%3}, {%4,%5,%6,%7}, {%8,%9}, {%0,%1,%2,%3};"
                 : "+f"(d[0]), "+f"(d[1]), "+f"(d[2]), "+f"(d[3])
                 : "r"(a[0]), "r"(a[1]), "r"(a[2]), "r"(a[3]), "r"(b[0]), "r"(b[1]));
}

__global__ void k_zero() {
    for (int i = threadIdx.x; i < NSTATS; i += blockDim.x) g_stats[i] = 0.f;
}

__global__ void k_w1r(const float* __restrict__ w1) {
    int i = blockIdx.x * blockDim.x + threadIdx.x;
    if (i >= COUT * CIN0) return;
    int o = i / CIN0, c = i % CIN0;
    float v;
    if (c < 256)      v = w1[o * 259 + 3 + c];
    else if (c < 259) v = w1[o * 259 + (c - 256)];
    else              v = 0.f;
    g_W1r[i] = v;
}

__global__ void k_s1(const float* __restrict__ feat, const float* __restrict__ sw1) {
    int blk = blockIdx.x;
    int b = blk >> 5;
    int m0 = (blk & 31) * 32;
    int tid = threadIdx.x;
    int mx = tid & 31, oy = tid >> 5;
    __shared__ float s_w[128][17];
    __shared__ float s_f[16][33];
    float acc[16];
    #pragma unroll
    for (int r = 0; r < 16; r++) acc[r] = 0.f;
    for (int c0 = 0; c0 < 256; c0 += 16) {
        __syncthreads();
        for (int idx = tid; idx < 128 * 16; idx += 256) {
            int o = idx >> 4, kk = idx & 15;
            s_w[o][kk] = sw1[o * 256 + c0 + kk];
        }
        for (int idx = tid; idx < 16 * 32; idx += 256) {
            int kk = idx >> 5, mm = idx & 31;
            s_f[kk][mm] = feat[((size_t)b * 256 + c0 + kk) * Mm + m0 + mm];
        }
        __syncthreads();
        #pragma unroll
        for (int r = 0; r < 16; r++) {
            int o = oy * 16 + r;
            #pragma unroll
            for (int kk = 0; kk < 16; kk++) acc[r] += s_w[o][kk] * s_f[kk][mx];
        }
    }
    #pragma unroll
    for (int r = 0; r < 16; r++) {
        int o = oy * 16 + r;
        float v = acc[r];
        g_h1[((size_t)b * 128 + o) * Mm + m0 + mx] = v;
        float s = wredsum(v), s2 = wredsum(v * v);
        if (mx == 0) {
            atomicAdd(&g_stats[SUM1 + o], s);
            atomicAdd(&g_stats[SQ1 + o], s2);
        }
    }
}

__global__ void k_fin(int n, int sumOff, int sqOff,
                      const float* __restrict__ gamma, const float* __restrict__ beta,
                      int which, float count) {
    int i = blockIdx.x * blockDim.x + threadIdx.x;
    if (i >= n) return;
    float mean = g_stats[sumOff + i] / count;
    float var  = g_stats[sqOff + i] / count - mean * mean;
    var = fmaxf(var, 0.f);
    float s = gamma[i] * rsqrtf(var + 1e-5f);
    float bi = beta[i] - mean * s;
    float *sc, *bb;
    if      (which == 0) { sc = g_sc1;    bb = g_bi1; }
    else if (which == 1) { sc = g_sc2;    bb = g_bi2; }
    else if (which == 2) { sc = g_scL[0]; bb = g_biL[0]; }
    else if (which == 3) { sc = g_scL[1]; bb = g_biL[1]; }
    else                 { sc = g_scL[2]; bb = g_biL[2]; }
    sc[i] = s; bb[i] = bi;
}

__global__ void k_s2(const float* __restrict__ sw2) {
    int b = blockIdx.x >> 3;
    int m0 = (blockIdx.x & 7) * 128;
    int tid = threadIdx.x;
    int m = m0 + tid;
    __shared__ float s_w[3][128];
    __shared__ float s_sc[128], s_bi[128];
    s_sc[tid] = g_sc1[tid];
    s_bi[tid] = g_bi1[tid];
    for (int i = tid; i < 384; i += 128) s_w[i / 128][i % 128] = sw2[i];
    __syncthreads();
    float a0 = 0.f, a1 = 0.f, a2 = 0.f;
    #pragma unroll 4
    for (int o = 0; o < 128; o++) {
        float h = g_h1[((size_t)b * 128 + o) * Mm + m];
        float x = fmaxf(h * s_sc[o] + s_bi[o], 0.f);
        a0 += s_w[0][o] * x;
        a1 += s_w[1][o] * x;
        a2 += s_w[2][o] * x;
    }
    g_h2[((size_t)b * 3 + 0) * Mm + m] = a0;
    g_h2[((size_t)b * 3 + 1) * Mm + m] = a1;
    g_h2[((size_t)b * 3 + 2) * Mm + m] = a2;
    float s, ss;
    s = wredsum(a0); ss = wredsum(a0 * a0);
    if ((tid & 31) == 0) { atomicAdd(&g_stats[SUM2 + 0], s); atomicAdd(&g_stats[SQ2 + 0], ss); }
    s = wredsum(a1); ss = wredsum(a1 * a1);
    if ((tid & 31) == 0) { atomicAdd(&g_stats[SUM2 + 1], s); atomicAdd(&g_stats[SQ2 + 1], ss); }
    s = wredsum(a2); ss = wredsum(a2 * a2);
    if ((tid & 31) == 0) { atomicAdd(&g_stats[SUM2 + 2], s); atomicAdd(&g_stats[SQ2 + 2], ss); }
}

__global__ void k_neigh(const float* __restrict__ fxyz, const float* __restrict__ bxyz) {
    int bm = blockIdx.x;
    int b = bm >> 10;
    int m = bm & 1023;
    int tid = threadIdx.x;
    __shared__ float q[3];
    __shared__ int list[Kk];
    __shared__ int cnt;
    __shared__ unsigned masks[8];
    if (tid == 0) cnt = 0;
    if (tid < 3) {
        float h = g_h2[((size_t)b * 3 + tid) * Mm + m];
        float sft = fmaxf(h * g_sc2[tid] + g_bi2[tid], 0.f);
        float qq = fxyz[((size_t)b * Mm + m) * 3 + tid] + sft;
        q[tid] = qq;
        g_q[((size_t)b * Mm + m) * 3 + tid] = qq;
    }
    __syncthreads();
    float qx = q[0], qy = q[1], qz = q[2];
    const float* bx = bxyz + (size_t)b * Nn * 3;
    int lane = tid & 31, wid = tid >> 5;
    for (int ch = 0; ch < Nn / 256; ch++) {
        int j = ch * 256 + tid;
        float dx = bx[j * 3 + 0] - qx;
        float dy = bx[j * 3 + 1] - qy;
        float dz = bx[j * 3 + 2] - qz;
        bool p = (dx * dx + dy * dy + dz * dz) < 1.0f;
        unsigned mk = __ballot_sync(0xFFFFFFFFu, p);
        if (lane == 0) masks[wid] = mk;
        __syncthreads();
        int before = cnt;
        for (int w = 0; w < wid; w++) before += __popc(masks[w]);
        if (p) {
            int pos = before + __popc(mk & ((1u << lane) - 1u));
            if (pos < Kk) list[pos] = j;
        }
        int total = 0;
        #pragma unroll
        for (int w = 0; w < 8; w++) total += __popc(masks[w]);
        __syncthreads();
        if (tid == 0) cnt += total;
        __syncthreads();
        if (cnt >= Kk) break;
    }
    if (tid < Kk) {
        int c = cnt;
        int v;
        if (c == 0)        v = 0;
        else if (tid < c)  v = list[tid];
        else               v = list[0];
        g_idx[bm * Kk + tid] = v;
    }
}

__global__ void k_transpose(const float* __restrict__ bf) {
    __shared__ float t[32][33];
    int b = blockIdx.z;
    int j0 = blockIdx.x * 32;
    int c0 = blockIdx.y * 32;
    int x = threadIdx.x, y = threadIdx.y;
    #pragma unroll
    for (int yy = y; yy < 32; yy += 8)
        t[yy][x] = bf[((size_t)b * Cc + c0 + yy) * Nn + j0 + x];
    __syncthreads();
    #pragma unroll
    for (int yy = y; yy < 32; yy += 8)
        g_featT[((size_t)b * Nn + j0 + yy) * Cc + c0 + x] = t[x][yy];
}

// ---- fp16 mma.sync GEMM: Y[P,512] = act(A[P,CIN]) @ W[512,CIN]^T ----
// CTA 128x128, 8 warps (wm in [0,4) -> 32 rows, wn in [0,2) -> 64 cols), KC=32.
// Layer 0: A gathered on the fly from featT/xyz via g_idx. Tiles in fp16 smem.
#define KC 32
#define LD2 20   // row stride in half2 units (bank-conflict-free fragments)

template <int LAYER>
__global__ void __launch_bounds__(256, 2) k_mma(const float* __restrict__ Wext,
                                                const float* __restrict__ bxyz) {
    constexpr int CIN = (LAYER == 0) ? CIN0 : COUT;
    constexpr int NCH = CIN / KC;
    constexpr int sumOff = SUML0 + LAYER * 1024;
    constexpr int sqOff  = sumOff + 512;
    const __half* Ah = (LAYER == 1) ? g_Y1 : g_Y2;   // LAYER 0 unused
    __half*       Y  = (LAYER == 0) ? g_Y1 : (LAYER == 1 ? g_Y2 : g_Y1);
    const float*  W  = (LAYER == 0) ? g_W1r : Wext;

    __shared__ uint32_t sA[2][128 * LD2];
    __shared__ uint32_t sB[2][128 * LD2];
    __shared__ float sSc[COUT], sBi[COUT];
    __shared__ float sPs[128], sPq[128];

    int tid = threadIdx.x;
    int lane = tid & 31, wrp = tid >> 5;
    int g = lane >> 2, t = lane & 3;
    int wm = wrp & 3, wn = wrp >> 2;
    int row0 = blockIdx.y * 128;
    int col0 = blockIdx.x * 128;

    if (LAYER > 0) {
        for (int c = tid; c < COUT; c += 256) {
            sSc[c] = g_scL[LAYER - 1][c];
            sBi[c] = g_biL[LAYER - 1][c];
        }
    }
    if (tid < 128) { sPs[tid] = 0.f; sPq[tid] = 0.f; }
    __syncthreads();

    float acc[2][8][4];
    #pragma unroll
    for (int i = 0; i < 2; i++)
        #pragma unroll
        for (int j = 0; j < 8; j++)
            #pragma unroll
            for (int r = 0; r < 4; r++) acc[i][j][r] = 0.f;

    float4 aS[4], bS[4];   // 32 floats each per thread per chunk

    auto ldg = [&](int c) {
        #pragma unroll
        for (int i = 0; i < 4; i++) {
            int idx = tid + i * 256;
            int r = idx >> 3, q = idx & 7;
            int cc = c * KC + q * 4;
            // ---- A ----
            if (LAYER == 0) {
                int p = row0 + r;
                if (cc < 256) {
                    int j = g_idx[p];
                    int b = p >> 15;
                    aS[i] = *(const float4*)(g_featT + ((size_t)b * Nn + j) * Cc + cc);
                } else if (cc == 256) {
                    int j = g_idx[p];
                    int b = p >> 15;
                    int bm = p >> 5;
                    const float* bx = bxyz + ((size_t)b * Nn + j) * 3;
                    aS[i].x = bx[0] - g_q[bm * 3 + 0];
                    aS[i].y = bx[1] - g_q[bm * 3 + 1];
                    aS[i].z = bx[2] - g_q[bm * 3 + 2];
                    aS[i].w = 0.f;
                } else {
                    aS[i] = make_float4(0.f, 0.f, 0.f, 0.f);
                }
            } else {
                const __half2* src = (const __half2*)(Ah + (size_t)(row0 + r) * COUT + cc);
                __half2 h0 = src[0], h1 = src[1];
                float2 f0 = __half22float2(h0), f1 = __half22float2(h1);
                float4 sc = *(const float4*)&sSc[cc];
                float4 bi = *(const float4*)&sBi[cc];
                aS[i].x = fmaxf(f0.x * sc.x + bi.x, 0.f);
                aS[i].y = fmaxf(f0.y * sc.y + bi.y, 0.f);
                aS[i].z = fmaxf(f1.x * sc.z + bi.z, 0.f);
                aS[i].w = fmaxf(f1.y * sc.w + bi.w, 0.f);
            }
            // ---- B ----
            bS[i] = *(const float4*)(W + (size_t)(col0 + r) * CIN + cc);
        }
    };
    auto sts = [&](int s) {
        #pragma unroll
        for (int i = 0; i < 4; i++) {
            int idx = tid + i * 256;
            int r = idx >> 3, q = idx & 7;
            sA[s][r * LD2 + q * 2 + 0] = packh2(aS[i].x, aS[i].y);
            sA[s][r * LD2 + q * 2 + 1] = packh2(aS[i].z, aS[i].w);
            sB[s][r * LD2 + q * 2 + 0] = packh2(bS[i].x, bS[i].y);
            sB[s][r * LD2 + q * 2 + 1] = packh2(bS[i].z, bS[i].w);
        }
    };
    auto compute = [&](int s) {
        const uint32_t* As = sA[s];
        const uint32_t* Bs = sB[s];
        #pragma unroll
        for (int ks = 0; ks < 2; ks++) {
            uint32_t af[2][4], bf[8][2];
            #pragma unroll
            for (int i = 0; i < 2; i++) {
                int rb = wm * 32 + i * 16 + g;
                af[i][0] = As[(rb    ) * LD2 + ks * 8 + t];
                af[i][1] = As[(rb + 8) * LD2 + ks * 8 + t];
                af[i][2] = As[(rb    ) * LD2 + ks * 8 + t + 4];
                af[i][3] = As[(rb + 8) * LD2 + ks * 8 + t + 4];
            }
            #pragma unroll
            for (int j = 0; j < 8; j++) {
                int cb = wn * 64 + j * 8 + g;
                bf[j][0] = Bs[cb * LD2 + ks * 8 + t];
                bf[j][1] = Bs[cb * LD2 + ks * 8 + t + 4];
            }
            #pragma unroll
            for (int i = 0; i < 2; i++)
                #pragma unroll
                for (int j = 0; j < 8; j++)
                    mma_f16(acc[i][j], af[i], bf[j]);
        }
    };

    ldg(0);
    sts(0);
    __syncthreads();
    for (int c = 0; c < NCH; c++) {
        int s = c & 1;
        if (c + 1 < NCH) ldg(c + 1);
        compute(s);
        if (c + 1 < NCH) {
            __syncthreads();
            sts(s ^ 1);
            __syncthreads();
        }
    }

    // ---- epilogue: store Y (fp16) + column stats (f32 acc) ----
    #pragma unroll
    for (int i = 0; i < 2; i++) {
        int rlo = row0 + wm * 32 + i * 16 + g;
        #pragma unroll
        for (int j = 0; j < 8; j++) {
            int col = col0 + wn * 64 + j * 8 + t * 2;
            *(uint32_t*)(Y + (size_t)rlo * COUT + col)       = packh2(acc[i][j][0], acc[i][j][1]);
            *(uint32_t*)(Y + (size_t)(rlo + 8) * COUT + col) = packh2(acc[i][j][2], acc[i][j][3]);
        }
    }
    #pragma unroll
    for (int j = 0; j < 8; j++) {
        #pragma unroll
        for (int rb = 0; rb < 2; rb++) {
            float s = 0.f, q2 = 0.f;
            #pragma unroll
            for (int i = 0; i < 2; i++) {
                float v0 = acc[i][j][rb], v1 = acc[i][j][rb + 2];
                s += v0 + v1;
                q2 += v0 * v0 + v1 * v1;
            }
            s  += __shfl_xor_sync(0xFFFFFFFFu, s, 4);
            q2 += __shfl_xor_sync(0xFFFFFFFFu, q2, 4);
            s  += __shfl_xor_sync(0xFFFFFFFFu, s, 8);
            q2 += __shfl_xor_sync(0xFFFFFFFFu, q2, 8);
            s  += __shfl_xor_sync(0xFFFFFFFFu, s, 16);
            q2 += __shfl_xor_sync(0xFFFFFFFFu, q2, 16);
            if (g == 0) {
                int cc = wn * 64 + j * 8 + t * 2 + rb;
                atomicAdd(&sPs[cc], s);
                atomicAdd(&sPq[cc], q2);
            }
        }
    }
    __syncthreads();
    if (tid < 128) {
        atomicAdd(&g_stats[sumOff + col0 + tid], sPs[tid]);
        atomicAdd(&g_stats[sqOff  + col0 + tid], sPq[tid]);
    }
}

__global__ void k_final(float* __restrict__ out) {
    int bm = blockIdx.x;
    int tid = threadIdx.x;
    const __half* base = g_Y1 + (size_t)bm * Kk * COUT;
    for (int o = tid; o < COUT; o += 256) {
        float s = g_scL[2][o], bi = g_biL[2][o];
        float mx = -1e30f;
        #pragma unroll 8
        for (int k = 0; k < Kk; k++) {
            float v = __half2float(base[(size_t)k * COUT + o]) * s + bi;
            mx = fmaxf(mx, v);
        }
        out[(size_t)bm * COUT + o] = fmaxf(mx, 0.f);
    }
}

extern "C" void kernel_launch(void* const* d_in, const int* in_sizes, int n_in,
                              void* d_out, int out_size) {
    const float* ffps_xyz     = (const float*)d_in[0];
    const float* ffps_feature = (const float*)d_in[1];
    const float* backbone_xyz = (const float*)d_in[2];
    const float* backbone_feat= (const float*)d_in[3];
    const float* sw1 = (const float*)d_in[4];
    const float* sg1 = (const float*)d_in[5];
    const float* sb1 = (const float*)d_in[6];
    const float* sw2 = (const float*)d_in[7];
    const float* sg2 = (const float*)d_in[8];
    const float* sb2 = (const float*)d_in[9];
    const float* w1  = (const float*)d_in[10];
    const float* g1  = (const float*)d_in[11];
    const float* b1  = (const float*)d_in[12];
    const float* w2  = (const float*)d_in[13];
    const float* g2  = (const float*)d_in[14];
    const float* b2  = (const float*)d_in[15];
    const float* w3  = (const float*)d_in[16];
    const float* g3  = (const float*)d_in[17];
    const float* b3  = (const float*)d_in[18];
    float* out = (float*)d_out;

    k_zero<<<1, 256>>>();
    k_w1r<<<(COUT * CIN0 + 255) / 256, 256>>>(w1);
    k_s1<<<Bb * (Mm / 32), 256>>>(ffps_feature, sw1);
    k_fin<<<1, 128>>>(128, SUM1, SQ1, sg1, sb1, 0, (float)(Bb * Mm));
    k_s2<<<Bb * (Mm / 128), 128>>>(sw2);
    k_fin<<<1, 32>>>(3, SUM2, SQ2, sg2, sb2, 1, (float)(Bb * Mm));
    k_neigh<<<Bb * Mm, 256>>>(ffps_xyz, backbone_xyz);
    k_transpose<<<dim3(Nn / 32, Cc / 32, Bb), dim3(32, 8)>>>(backbone_feat);

    dim3 grid(COUT / 128, Pp / 128);   // x = N block (fast) for A-tile L2 reuse
    k_mma<0><<<grid, 256>>>(nullptr, backbone_xyz);
    k_fin<<<2, 256>>>(512, SUML0 + 0 * 1024, SUML0 + 0 * 1024 + 512, g1, b1, 2, (float)Pp);
    k_mma<1><<<grid, 256>>>(w2, nullptr);
    k_fin<<<2, 256>>>(512, SUML0 + 1 * 1024, SUML0 + 1 * 1024 + 512, g2, b2, 3, (float)Pp);
    k_mma<2><<<grid, 256>>>(w3, nullptr);
    k_fin<<<2, 256>>>(512, SUML0 + 2 * 1024, SUML0 + 2 * 1024 + 512, g3, b3, 4, (float)Pp);

    k_final<<<Bb * Mm, 256>>>(out);
}

// round 6
// speedup vs baseline: 3.5735x; 1.0191x over previous
#include <cuda_runtime.h>
#include <cuda_fp16.h>
#include <math.h>
#include <stdint.h>

#define Bb 4
#define Nn 16384
#define Mm 1024
#define Cc 256
#define Kk 32
#define Pp (Bb*Mm*Kk)
#define CIN0 288
#define COUT 512

#define SUM1 0
#define SQ1  128
#define SUM2 256
#define SQ2  260
#define SUML0 264
#define NSTATS (264 + 3*1024)

__device__ __align__(128) float  g_featT[(size_t)Bb*Nn*Cc];
__device__ __align__(128) __half g_Y1[(size_t)Pp*COUT];
__device__ __align__(128) __half g_Y2[(size_t)Pp*COUT];
__device__ __align__(128) float  g_h1[Bb*128*Mm];
__device__ __align__(128) float  g_h2[Bb*3*Mm];
__device__ __align__(128) float  g_q[Bb*Mm*3];
__device__ __align__(128) int    g_idx[Pp];
__device__ __align__(128) __half g_W1h[COUT*CIN0];
__device__ __align__(128) __half g_W2h[COUT*COUT];
__device__ __align__(128) __half g_W3h[COUT*COUT];
__device__ __align__(128) float  g_stats[NSTATS];
__device__ float g_sc1[128], g_bi1[128];
__device__ float g_sc2[4],   g_bi2[4];
__device__ float g_scL[3][COUT], g_biL[3][COUT];

__device__ __forceinline__ float wredsum(float v) {
    #pragma unroll
    for (int o = 16; o > 0; o >>= 1) v += __shfl_xor_sync(0xFFFFFFFFu, v, o);
    return v;
}
__device__ __forceinline__ uint32_t packh2(float a, float b) {
    __half2 h = __floats2half2_rn(a, b);
    return *(uint32_t*)&h;
}
__device__ __forceinline__ uint32_t smem_u32(const void* p) {
    uint32_t a;
    asm("{ .reg .u64 t; cvta.to.shared.u64 t, %1; cvt.u32.u64 %0, t; }" : "=r"(a) : "l"(p));
    return a;
}
__device__ __forceinline__ void mma_f16(float* d, const uint32_t* a, const uint32_t* b) {
    asm volatile("mma.sync.aligned.m16n8k16.row.col.f32.f16.f16.f32 "
                 "{%0,%1,%2,%3}, {%4,%5,%6,%7}, {%8,%9}, {%0,%1,%2,%3};"
                 : "+f"(d[0]), "+f"(d[1]), "+f"(d[2]), "+f"(d[3])
                 : "r"(a[0]), "r"(a[1]), "r"(a[2]), "r"(a[3]), "r"(b[0]), "r"(b[1]));
}
__device__ __forceinline__ void ldsm_x4(uint32_t& r0, uint32_t& r1, uint32_t& r2, uint32_t& r3, uint32_t addr) {
    asm volatile("ldmatrix.sync.aligned.m8n8.x4.shared.b16 {%0,%1,%2,%3}, [%4];"
                 : "=r"(r0), "=r"(r1), "=r"(r2), "=r"(r3) : "r"(addr));
}

// prep: zero stats, repack w1->fp16 (feat|xyz|pad layout), convert w2/w3->fp16
__global__ void k_prep(const float* __restrict__ w1, const float* __restrict__ w2,
                       const float* __restrict__ w3) {
    int i = blockIdx.x * blockDim.x + threadIdx.x;
    if (i < NSTATS) g_stats[i] = 0.f;
    if (i < COUT * CIN0) {
        int o = i / CIN0, c = i % CIN0;
        float v;
        if (c < 256)      v = w1[o * 259 + 3 + c];
        else if (c < 259) v = w1[o * 259 + (c - 256)];
        else              v = 0.f;
        g_W1h[i] = __float2half(v);
    }
    if (i < COUT * COUT) {
        g_W2h[i] = __float2half(w2[i]);
        g_W3h[i] = __float2half(w3[i]);
    }
}

__global__ void k_s1(const float* __restrict__ feat, const float* __restrict__ sw1) {
    int blk = blockIdx.x;
    int b = blk >> 5;
    int m0 = (blk & 31) * 32;
    int tid = threadIdx.x;
    int mx = tid & 31, oy = tid >> 5;
    __shared__ float s_w[128][17];
    __shared__ float s_f[16][33];
    float acc[16];
    #pragma unroll
    for (int r = 0; r < 16; r++) acc[r] = 0.f;
    for (int c0 = 0; c0 < 256; c0 += 16) {
        __syncthreads();
        for (int idx = tid; idx < 128 * 16; idx += 256) {
            int o = idx >> 4, kk = idx & 15;
            s_w[o][kk] = sw1[o * 256 + c0 + kk];
        }
        for (int idx = tid; idx < 16 * 32; idx += 256) {
            int kk = idx >> 5, mm = idx & 31;
            s_f[kk][mm] = feat[((size_t)b * 256 + c0 + kk) * Mm + m0 + mm];
        }
        __syncthreads();
        #pragma unroll
        for (int r = 0; r < 16; r++) {
            int o = oy * 16 + r;
            #pragma unroll
            for (int kk = 0; kk < 16; kk++) acc[r] += s_w[o][kk] * s_f[kk][mx];
        }
    }
    #pragma unroll
    for (int r = 0; r < 16; r++) {
        int o = oy * 16 + r;
        float v = acc[r];
        g_h1[((size_t)b * 128 + o) * Mm + m0 + mx] = v;
        float s = wredsum(v), s2 = wredsum(v * v);
        if (mx == 0) {
            atomicAdd(&g_stats[SUM1 + o], s);
            atomicAdd(&g_stats[SQ1 + o], s2);
        }
    }
}

__global__ void k_fin(int n, int sumOff, int sqOff,
                      const float* __restrict__ gamma, const float* __restrict__ beta,
                      int which, float count) {
    int i = blockIdx.x * blockDim.x + threadIdx.x;
    if (i >= n) return;
    float mean = g_stats[sumOff + i] / count;
    float var  = g_stats[sqOff + i] / count - mean * mean;
    var = fmaxf(var, 0.f);
    float s = gamma[i] * rsqrtf(var + 1e-5f);
    float bi = beta[i] - mean * s;
    float *sc, *bb;
    if      (which == 0) { sc = g_sc1;    bb = g_bi1; }
    else if (which == 1) { sc = g_sc2;    bb = g_bi2; }
    else                 { sc = g_scL[2]; bb = g_biL[2]; }
    sc[i] = s; bb[i] = bi;
}

__global__ void k_s2(const float* __restrict__ sw2) {
    int b = blockIdx.x >> 3;
    int m0 = (blockIdx.x & 7) * 128;
    int tid = threadIdx.x;
    int m = m0 + tid;
    __shared__ float s_w[3][128];
    __shared__ float s_sc[128], s_bi[128];
    s_sc[tid] = g_sc1[tid];
    s_bi[tid] = g_bi1[tid];
    for (int i = tid; i < 384; i += 128) s_w[i / 128][i % 128] = sw2[i];
    __syncthreads();
    float a0 = 0.f, a1 = 0.f, a2 = 0.f;
    #pragma unroll 4
    for (int o = 0; o < 128; o++) {
        float h = g_h1[((size_t)b * 128 + o) * Mm + m];
        float x = fmaxf(h * s_sc[o] + s_bi[o], 0.f);
        a0 += s_w[0][o] * x;
        a1 += s_w[1][o] * x;
        a2 += s_w[2][o] * x;
    }
    g_h2[((size_t)b * 3 + 0) * Mm + m] = a0;
    g_h2[((size_t)b * 3 + 1) * Mm + m] = a1;
    g_h2[((size_t)b * 3 + 2) * Mm + m] = a2;
    float s, ss;
    s = wredsum(a0); ss = wredsum(a0 * a0);
    if ((tid & 31) == 0) { atomicAdd(&g_stats[SUM2 + 0], s); atomicAdd(&g_stats[SQ2 + 0], ss); }
    s = wredsum(a1); ss = wredsum(a1 * a1);
    if ((tid & 31) == 0) { atomicAdd(&g_stats[SUM2 + 1], s); atomicAdd(&g_stats[SQ2 + 1], ss); }
    s = wredsum(a2); ss = wredsum(a2 * a2);
    if ((tid & 31) == 0) { atomicAdd(&g_stats[SUM2 + 2], s); atomicAdd(&g_stats[SQ2 + 2], ss); }
}

__global__ void k_neigh(const float* __restrict__ fxyz, const float* __restrict__ bxyz) {
    int bm = blockIdx.x;
    int b = bm >> 10;
    int m = bm & 1023;
    int tid = threadIdx.x;
    __shared__ float q[3];
    __shared__ int list[Kk];
    __shared__ int cnt;
    __shared__ unsigned masks[8];
    if (tid == 0) cnt = 0;
    if (tid < 3) {
        float h = g_h2[((size_t)b * 3 + tid) * Mm + m];
        float sft = fmaxf(h * g_sc2[tid] + g_bi2[tid], 0.f);
        float qq = fxyz[((size_t)b * Mm + m) * 3 + tid] + sft;
        q[tid] = qq;
        g_q[((size_t)b * Mm + m) * 3 + tid] = qq;
    }
    __syncthreads();
    float qx = q[0], qy = q[1], qz = q[2];
    const float* bx = bxyz + (size_t)b * Nn * 3;
    int lane = tid & 31, wid = tid >> 5;
    for (int ch = 0; ch < Nn / 256; ch++) {
        int j = ch * 256 + tid;
        float dx = bx[j * 3 + 0] - qx;
        float dy = bx[j * 3 + 1] - qy;
        float dz = bx[j * 3 + 2] - qz;
        bool p = (dx * dx + dy * dy + dz * dz) < 1.0f;
        unsigned mk = __ballot_sync(0xFFFFFFFFu, p);
        if (lane == 0) masks[wid] = mk;
        __syncthreads();
        int before = cnt;
        for (int w = 0; w < wid; w++) before += __popc(masks[w]);
        if (p) {
            int pos = before + __popc(mk & ((1u << lane) - 1u));
            if (pos < Kk) list[pos] = j;
        }
        int total = 0;
        #pragma unroll
        for (int w = 0; w < 8; w++) total += __popc(masks[w]);
        __syncthreads();
        if (tid == 0) cnt += total;
        __syncthreads();
        if (cnt >= Kk) break;
    }
    if (tid < Kk) {
        int c = cnt;
        int v;
        if (c == 0)        v = 0;
        else if (tid < c)  v = list[tid];
        else               v = list[0];
        g_idx[bm * Kk + tid] = v;
    }
}

__global__ void k_transpose(const float* __restrict__ bf) {
    __shared__ float t[32][33];
    int b = blockIdx.z;
    int j0 = blockIdx.x * 32;
    int c0 = blockIdx.y * 32;
    int x = threadIdx.x, y = threadIdx.y;
    #pragma unroll
    for (int yy = y; yy < 32; yy += 8)
        t[yy][x] = bf[((size_t)b * Cc + c0 + yy) * Nn + j0 + x];
    __syncthreads();
    #pragma unroll
    for (int yy = y; yy < 32; yy += 8)
        g_featT[((size_t)b * Nn + j0 + yy) * Cc + c0 + x] = t[x][yy];
}

// ---- fp16 mma.sync GEMM with ldmatrix fragments ----
// CTA 128x128, 8 warps (wm 32 rows, wn 64 cols), KC=32, fp16 weights/acts.
#define KC 32
#define LD2 20                  // row stride in uint32 (half2) units
#define STGW (128 * LD2)        // words per stage

template <int LAYER>
__global__ void __launch_bounds__(256, 2) k_mma(const float* __restrict__ gamPrev,
                                                const float* __restrict__ betPrev,
                                                const float* __restrict__ bxyz) {
    constexpr int CIN = (LAYER == 0) ? CIN0 : COUT;
    constexpr int NCH = CIN / KC;
    constexpr int sumOff = SUML0 + LAYER * 1024;
    constexpr int sqOff  = sumOff + 512;
    const __half* Ah = (LAYER == 1) ? g_Y1 : g_Y2;   // LAYER 0 unused
    __half*       Y  = (LAYER == 0) ? g_Y1 : (LAYER == 1 ? g_Y2 : g_Y1);
    const __half* W  = (LAYER == 0) ? g_W1h : (LAYER == 1 ? g_W2h : g_W3h);

    __shared__ uint32_t sA[2 * STGW];
    __shared__ uint32_t sB[2 * STGW];
    __shared__ float sSc[COUT], sBi[COUT];
    __shared__ float sPs[128], sPq[128];

    int tid = threadIdx.x;
    int lane = tid & 31, wrp = tid >> 5;
    int g = lane >> 2, t = lane & 3;
    int wm = wrp & 3, wn = wrp >> 2;
    int row0 = blockIdx.y * 128;
    int col0 = blockIdx.x * 128;

    if (LAYER > 0) {
        // fold BN finalize of previous layer into prologue
        const float invP = 1.f / (float)Pp;
        int pOff = SUML0 + (LAYER - 1) * 1024;
        for (int c = tid; c < COUT; c += 256) {
            float mean = g_stats[pOff + c] * invP;
            float var  = g_stats[pOff + 512 + c] * invP - mean * mean;
            var = fmaxf(var, 0.f);
            float s = gamPrev[c] * rsqrtf(var + 1e-5f);
            sSc[c] = s;
            sBi[c] = betPrev[c] - mean * s;
        }
    }
    if (tid < 128) { sPs[tid] = 0.f; sPq[tid] = 0.f; }
    __syncthreads();

    uint32_t sbA = smem_u32(sA), sbB = smem_u32(sB);
    // per-lane ldmatrix byte offsets
    uint32_t aoff[2], boff[4];
    #pragma unroll
    for (int i = 0; i < 2; i++)
        aoff[i] = (((wm * 32 + i * 16 + (lane & 15)) * LD2 + ((lane >> 4) << 2)) << 2);
    #pragma unroll
    for (int jp = 0; jp < 4; jp++)
        boff[jp] = (((wn * 64 + jp * 16 + ((lane >> 4) & 1) * 8 + (lane & 7)) * LD2
                     + ((lane >> 3) & 1) * 4) << 2);

    float acc[2][8][4];
    #pragma unroll
    for (int i = 0; i < 2; i++)
        #pragma unroll
        for (int j = 0; j < 8; j++)
            #pragma unroll
            for (int r = 0; r < 4; r++) acc[i][j][r] = 0.f;

    uint32_t aW[2][4], bW[2][4];   // staged words (2 units of 4 words each)

    auto ldg = [&](int c) {
        #pragma unroll
        for (int i = 0; i < 2; i++) {
            int idx = tid + i * 256;
            int r = idx >> 2, q = idx & 3;
            int cc = c * KC + q * 8;
            // ---- A (8 halves) ----
            if (LAYER == 0) {
                int p = row0 + r;
                if (cc < 256) {
                    int j = g_idx[p];
                    int b = p >> 15;
                    const float* src = g_featT + ((size_t)b * Nn + j) * Cc + cc;
                    float4 f0 = *(const float4*)(src);
                    float4 f1 = *(const float4*)(src + 4);
                    aW[i][0] = packh2(f0.x, f0.y);
                    aW[i][1] = packh2(f0.z, f0.w);
                    aW[i][2] = packh2(f1.x, f1.y);
                    aW[i][3] = packh2(f1.z, f1.w);
                } else if (cc == 256) {
                    int j = g_idx[p];
                    int b = p >> 15;
                    int bm = p >> 5;
                    const float* bx = bxyz + ((size_t)b * Nn + j) * 3;
                    aW[i][0] = packh2(bx[0] - g_q[bm * 3 + 0], bx[1] - g_q[bm * 3 + 1]);
                    aW[i][1] = packh2(bx[2] - g_q[bm * 3 + 2], 0.f);
                    aW[i][2] = 0u; aW[i][3] = 0u;
                } else {
                    aW[i][0] = 0u; aW[i][1] = 0u; aW[i][2] = 0u; aW[i][3] = 0u;
                }
            } else {
                uint4 raw = *(const uint4*)(Ah + (size_t)(row0 + r) * COUT + cc);
                uint32_t rw[4] = {raw.x, raw.y, raw.z, raw.w};
                #pragma unroll
                for (int w = 0; w < 4; w++) {
                    float2 f = __half22float2(*(__half2*)&rw[w]);
                    float s0 = sSc[cc + w * 2], s1 = sSc[cc + w * 2 + 1];
                    float b0 = sBi[cc + w * 2], b1 = sBi[cc + w * 2 + 1];
                    aW[i][w] = packh2(fmaxf(f.x * s0 + b0, 0.f), fmaxf(f.y * s1 + b1, 0.f));
                }
            }
            // ---- B (8 halves, already fp16) ----
            uint4 wb = *(const uint4*)(W + (size_t)(col0 + r) * CIN + cc);
            bW[i][0] = wb.x; bW[i][1] = wb.y; bW[i][2] = wb.z; bW[i][3] = wb.w;
        }
    };
    auto sts = [&](int s) {
        #pragma unroll
        for (int i = 0; i < 2; i++) {
            int idx = tid + i * 256;
            int r = idx >> 2, q = idx & 3;
            *(uint4*)&sA[s * STGW + r * LD2 + q * 4] = make_uint4(aW[i][0], aW[i][1], aW[i][2], aW[i][3]);
            *(uint4*)&sB[s * STGW + r * LD2 + q * 4] = make_uint4(bW[i][0], bW[i][1], bW[i][2], bW[i][3]);
        }
    };
    auto compute = [&](int s) {
        uint32_t aB = sbA + s * (STGW * 4);
        uint32_t bB = sbB + s * (STGW * 4);
        #pragma unroll
        for (int ks = 0; ks < 2; ks++) {
            uint32_t af[2][4], bf[8][2];
            #pragma unroll
            for (int i = 0; i < 2; i++)
                ldsm_x4(af[i][0], af[i][1], af[i][2], af[i][3], aB + aoff[i] + ks * 32);
            #pragma unroll
            for (int jp = 0; jp < 4; jp++)
                ldsm_x4(bf[jp * 2][0], bf[jp * 2][1], bf[jp * 2 + 1][0], bf[jp * 2 + 1][1],
                        bB + boff[jp] + ks * 32);
            #pragma unroll
            for (int i = 0; i < 2; i++)
                #pragma unroll
                for (int j = 0; j < 8; j++)
                    mma_f16(acc[i][j], af[i], bf[j]);
        }
    };

    ldg(0);
    sts(0);
    __syncthreads();
    for (int c = 0; c < NCH; c++) {
        int s = c & 1;
        if (c + 1 < NCH) ldg(c + 1);
        compute(s);
        if (c + 1 < NCH) {
            __syncthreads();
            sts(s ^ 1);
            __syncthreads();
        }
    }

    // ---- epilogue: store Y (fp16) + column stats (f32) ----
    #pragma unroll
    for (int i = 0; i < 2; i++) {
        int rlo = row0 + wm * 32 + i * 16 + g;
        #pragma unroll
        for (int j = 0; j < 8; j++) {
            int col = col0 + wn * 64 + j * 8 + t * 2;
            *(uint32_t*)(Y + (size_t)rlo * COUT + col)       = packh2(acc[i][j][0], acc[i][j][1]);
            *(uint32_t*)(Y + (size_t)(rlo + 8) * COUT + col) = packh2(acc[i][j][2], acc[i][j][3]);
        }
    }
    #pragma unroll
    for (int j = 0; j < 8; j++) {
        #pragma unroll
        for (int rb = 0; rb < 2; rb++) {
            float s = 0.f, q2 = 0.f;
            #pragma unroll
            for (int i = 0; i < 2; i++) {
                float v0 = acc[i][j][rb], v1 = acc[i][j][rb + 2];
                s += v0 + v1;
                q2 += v0 * v0 + v1 * v1;
            }
            s  += __shfl_xor_sync(0xFFFFFFFFu, s, 4);
            q2 += __shfl_xor_sync(0xFFFFFFFFu, q2, 4);
            s  += __shfl_xor_sync(0xFFFFFFFFu, s, 8);
            q2 += __shfl_xor_sync(0xFFFFFFFFu, q2, 8);
            s  += __shfl_xor_sync(0xFFFFFFFFu, s, 16);
            q2 += __shfl_xor_sync(0xFFFFFFFFu, q2, 16);
            if (g == 0) {
                int cc = wn * 64 + j * 8 + t * 2 + rb;
                atomicAdd(&sPs[cc], s);
                atomicAdd(&sPq[cc], q2);
            }
        }
    }
    __syncthreads();
    if (tid < 128) {
        atomicAdd(&g_stats[sumOff + col0 + tid], sPs[tid]);
        atomicAdd(&g_stats[sqOff  + col0 + tid], sPq[tid]);
    }
}

__global__ void k_final(float* __restrict__ out) {
    int bm = blockIdx.x;
    int tid = threadIdx.x;
    const __half* base = g_Y1 + (size_t)bm * Kk * COUT;
    for (int o = tid; o < COUT; o += 256) {
        float s = g_scL[2][o], bi = g_biL[2][o];
        float mx = -1e30f;
        #pragma unroll 8
        for (int k = 0; k < Kk; k++) {
            float v = __half2float(base[(size_t)k * COUT + o]) * s + bi;
            mx = fmaxf(mx, v);
        }
        out[(size_t)bm * COUT + o] = fmaxf(mx, 0.f);
    }
}

extern "C" void kernel_launch(void* const* d_in, const int* in_sizes, int n_in,
                              void* d_out, int out_size) {
    const float* ffps_xyz     = (const float*)d_in[0];
    const float* ffps_feature = (const float*)d_in[1];
    const float* backbone_xyz = (const float*)d_in[2];
    const float* backbone_feat= (const float*)d_in[3];
    const float* sw1 = (const float*)d_in[4];
    const float* sg1 = (const float*)d_in[5];
    const float* sb1 = (const float*)d_in[6];
    const float* sw2 = (const float*)d_in[7];
    const float* sg2 = (const float*)d_in[8];
    const float* sb2 = (const float*)d_in[9];
    const float* w1  = (const float*)d_in[10];
    const float* g1  = (const float*)d_in[11];
    const float* b1  = (const float*)d_in[12];
    const float* w2  = (const float*)d_in[13];
    const float* g2  = (const float*)d_in[14];
    const float* b2  = (const float*)d_in[15];
    const float* w3  = (const float*)d_in[16];
    const float* g3  = (const float*)d_in[17];
    const float* b3  = (const float*)d_in[18];
    float* out = (float*)d_out;

    k_prep<<<(COUT * COUT + 255) / 256, 256>>>(w1, w2, w3);
    k_s1<<<Bb * (Mm / 32), 256>>>(ffps_feature, sw1);
    k_fin<<<1, 128>>>(128, SUM1, SQ1, sg1, sb1, 0, (float)(Bb * Mm));
    k_s2<<<Bb * (Mm / 128), 128>>>(sw2);
    k_fin<<<1, 32>>>(3, SUM2, SQ2, sg2, sb2, 1, (float)(Bb * Mm));
    k_neigh<<<Bb * Mm, 256>>>(ffps_xyz, backbone_xyz);
    k_transpose<<<dim3(Nn / 32, Cc / 32, Bb), dim3(32, 8)>>>(backbone_feat);

    dim3 grid(COUT / 128, Pp / 128);   // x = N block (fast) for A-tile L2 reuse
    k_mma<0><<<grid, 256>>>(nullptr, nullptr, backbone_xyz);
    k_mma<1><<<grid, 256>>>(g1, b1, nullptr);
    k_mma<2><<<grid, 256>>>(g2, b2, nullptr);
    k_fin<<<2, 256>>>(512, SUML0 + 2 * 1024, SUML0 + 2 * 1024 + 512, g3, b3, 4, (float)Pp);

    k_final<<<Bb * Mm, 256>>>(out);
}